// round 10
// baseline (speedup 1.0000x reference)
#include <cuda_runtime.h>
#include <cuda_bf16.h>
#include <math.h>
#include <stdint.h>

#define N_NODES 100000
#define N_EDGES 1000000
#define FEAT 64
#define N_GRAPHS 512
#define N_CLS 10
#define BN_EPS 1e-5f
#define CAP 96

#define NTILES 782
#define GRID_CONV 296

// Scratch (device globals — no allocation allowed)
__device__ float g_h1[N_NODES * FEAT];
__device__ float g_sums[N_GRAPHS * FEAT];
__device__ float g_cnts[N_GRAPHS];
__device__ int   g_deg[N_NODES];
__device__ int   g_csr[N_NODES * CAP];

// ---------------------------------------------------------------------------
// helpers
// ---------------------------------------------------------------------------
__device__ __forceinline__ uint32_t f2tf32(float x) {
    uint32_t r;
    asm("cvt.rna.tf32.f32 %0, %1;" : "=r"(r) : "f"(x));
    return r;
}

__device__ __forceinline__ void mma_tf32(float* c, const uint32_t* a,
                                         uint32_t b0, uint32_t b1) {
    asm("mma.sync.aligned.m16n8k8.row.col.f32.tf32.tf32.f32 "
        "{%0,%1,%2,%3}, {%4,%5,%6,%7}, {%8,%9}, {%0,%1,%2,%3};"
        : "+f"(c[0]), "+f"(c[1]), "+f"(c[2]), "+f"(c[3])
        : "r"(a[0]), "r"(a[1]), "r"(a[2]), "r"(a[3]), "r"(b0), "r"(b1));
}

#define BAR_SYNC(id, cnt) \
    asm volatile("bar.sync %0, %1;" :: "n"(id), "n"(cnt) : "memory")
#define BAR_ARRIVE(id, cnt) \
    asm volatile("bar.arrive %0, %1;" :: "n"(id), "n"(cnt) : "memory")

// SMEM layout (bytes)
#define A_STRIDE 68
#define W_STRIDE 72
#define ABYTES   34816                      // 128 * 68 * 4
#define SM_W1    (2 * ABYTES)               // 69632
#define SM_W2    (SM_W1 + 18432)            // 88064
#define SM_B0    (SM_W2 + 18432)            // 106496
#define SM_B1    (SM_B0 + 256)              // 106752
#define SM_BAT   (SM_B1 + 256)              // 107008
#define SM_TOTAL (SM_BAT + 1024)            // 108032

// ---------------------------------------------------------------------------
// CSR fill: csr[dst*CAP + pos] = src
// ---------------------------------------------------------------------------
__global__ __launch_bounds__(256) void fill_kernel(
    const int* __restrict__ src, const int* __restrict__ dst,
    int* __restrict__ deg, int* __restrict__ csr)
{
    int e = blockIdx.x * blockDim.x + threadIdx.x;
    if (e >= N_EDGES) return;
    int d = __ldg(dst + e);
    int pos = atomicAdd(deg + d, 1);
    if (pos < CAP) csr[d * CAP + pos] = __ldg(src + e);
}

// ---------------------------------------------------------------------------
__global__ __launch_bounds__(256) void count_kernel(
    const int* __restrict__ batch, float* __restrict__ cnts)
{
    int i = blockIdx.x * blockDim.x + threadIdx.x;
    if (i < N_NODES) atomicAdd(cnts + __ldg(batch + i), 1.0f);
}

// ---------------------------------------------------------------------------
// Fused gather + GIN MLP, warp-specialized persistent kernel.
// Warps 4-7 (producers): pull-gather t = h[node] + sum h[nbr] for tile i+1
//   into double-buffered SMEM.
// Warps 0-3 (consumers): two tf32 mma.sync layers + epilogue on tile i.
// Named barriers: 1+buf = buffer ready (P arrive / C sync),
//                 3+buf = buffer free  (C arrive / P sync),
//                 5     = consumer-internal (128 threads).
// mode 0: out[node] = relu(mlp(t))
// mode 1: segmented block-reduce mlp(t) rows by sorted batch -> red to sums
// ---------------------------------------------------------------------------
__global__ __launch_bounds__(256, 2) void conv_kernel(
    const float* __restrict__ h,
    const int* __restrict__ deg, const int* __restrict__ csr,
    const float* __restrict__ wa, const float* __restrict__ ba,
    const float* __restrict__ gam, const float* __restrict__ bet,
    const float* __restrict__ mu,  const float* __restrict__ var,
    const float* __restrict__ wb,  const float* __restrict__ bb,
    float* __restrict__ out, const int* __restrict__ batch,
    float* __restrict__ sums, int mode)
{
    extern __shared__ __align__(16) char sm[];
    float* W1_s = (float*)(sm + SM_W1);
    float* W2_s = (float*)(sm + SM_W2);
    float* b0_s = (float*)(sm + SM_B0);
    float* b1_s = (float*)(sm + SM_B1);

    int tid = threadIdx.x;
    int wid = tid >> 5;

    if (wid >= 4) {
        // ================= PRODUCERS (warps 4-7) =================
        int ptid = tid - 128;      // 0..127
        int prow = ptid >> 4;      // 0..7
        int pc = ptid & 15;        // float4 column

        int it = 0;
        for (int tile = blockIdx.x; tile < NTILES; tile += GRID_CONV, it++) {
            int buf = it & 1;
            if (buf) { if (it >= 2) BAR_SYNC(4, 256); }
            else     { if (it >= 2) BAR_SYNC(3, 256); }

            float* A_s = (float*)(sm + buf * ABYTES);
            int* bat_s = (int*)(sm + SM_BAT + buf * 512);

            for (int s = 0; s < 16; s++) {
                int row = s * 8 + prow;
                int node = tile * 128 + row;
                float4 acc = make_float4(0.f, 0.f, 0.f, 0.f);
                if (node < N_NODES) {
                    acc = __ldg(reinterpret_cast<const float4*>(
                              h + (size_t)node * FEAT) + pc);
                    int dg = __ldg(deg + node);
                    if (dg > CAP) dg = CAP;
                    const int* lst = csr + (size_t)node * CAP;
                    int i = 0;
                    for (; i + 4 <= dg; i += 4) {
                        int s0 = __ldg(lst + i);
                        int s1 = __ldg(lst + i + 1);
                        int s2 = __ldg(lst + i + 2);
                        int s3 = __ldg(lst + i + 3);
                        float4 a = __ldg(reinterpret_cast<const float4*>(h + (size_t)s0 * FEAT) + pc);
                        float4 b = __ldg(reinterpret_cast<const float4*>(h + (size_t)s1 * FEAT) + pc);
                        float4 d = __ldg(reinterpret_cast<const float4*>(h + (size_t)s2 * FEAT) + pc);
                        float4 e = __ldg(reinterpret_cast<const float4*>(h + (size_t)s3 * FEAT) + pc);
                        acc.x += a.x; acc.y += a.y; acc.z += a.z; acc.w += a.w;
                        acc.x += b.x; acc.y += b.y; acc.z += b.z; acc.w += b.w;
                        acc.x += d.x; acc.y += d.y; acc.z += d.z; acc.w += d.w;
                        acc.x += e.x; acc.y += e.y; acc.z += e.z; acc.w += e.w;
                    }
                    for (; i < dg; i++) {
                        int s0 = __ldg(lst + i);
                        float4 a = __ldg(reinterpret_cast<const float4*>(h + (size_t)s0 * FEAT) + pc);
                        acc.x += a.x; acc.y += a.y; acc.z += a.z; acc.w += a.w;
                    }
                }
                *reinterpret_cast<float4*>(A_s + row * A_STRIDE + pc * 4) = acc;
                if (pc == 0)
                    bat_s[row] = (node < N_NODES) ? __ldg(batch + node) : -1;
            }
            __threadfence_block();
            if (buf) BAR_ARRIVE(2, 256);
            else     BAR_ARRIVE(1, 256);
        }
    } else {
        // ================= CONSUMERS (warps 0-3) =================
        int lane = tid & 31;
        int g = lane >> 2;
        int t = lane & 3;
        int mw = wid;

        // stage weights once (BN folded into W1), tf32-rounded
        for (int i = tid; i < FEAT * FEAT; i += 128) {
            int n = i & 63;
            float s = __ldg(gam + n) * rsqrtf(__ldg(var + n) + BN_EPS);
            W1_s[(i >> 6) * W_STRIDE + n] = __uint_as_float(f2tf32(__ldg(wa + i) * s));
            W2_s[(i >> 6) * W_STRIDE + n] = __uint_as_float(f2tf32(__ldg(wb + i)));
        }
        if (tid < FEAT) {
            float s = __ldg(gam + tid) * rsqrtf(__ldg(var + tid) + BN_EPS);
            b0_s[tid] = (__ldg(ba + tid) - __ldg(mu + tid)) * s + __ldg(bet + tid);
            b1_s[tid] = __ldg(bb + tid);
        }
        BAR_SYNC(5, 128);

        int it = 0;
        for (int tile = blockIdx.x; tile < NTILES; tile += GRID_CONV, it++) {
            int buf = it & 1;
            if (buf) BAR_SYNC(2, 256);
            else     BAR_SYNC(1, 256);

            float* A_s = (float*)(sm + buf * ABYTES);
            int* bat_s = (int*)(sm + SM_BAT + buf * 512);
            const float* Aw = A_s + (mw * 32) * A_STRIDE;
            float* Aww = A_s + (mw * 32) * A_STRIDE;
            int node_base = tile * 128;

            float acc[2][8][4];

#define GEMM_LAYER(WS)                                                        \
    {                                                                         \
        _Pragma("unroll")                                                     \
        for (int mt = 0; mt < 2; mt++)                                        \
            _Pragma("unroll")                                                 \
            for (int nt = 0; nt < 8; nt++)                                    \
                _Pragma("unroll")                                             \
                for (int e = 0; e < 4; e++) acc[mt][nt][e] = 0.0f;            \
        _Pragma("unroll")                                                     \
        for (int ks = 0; ks < 8; ks++) {                                      \
            uint32_t af[2][4];                                                \
            _Pragma("unroll")                                                 \
            for (int mt = 0; mt < 2; mt++) {                                  \
                const float* ap = Aw + (mt * 16 + g) * A_STRIDE + ks * 8 + t; \
                af[mt][0] = f2tf32(ap[0]);                                    \
                af[mt][1] = f2tf32(ap[8 * A_STRIDE]);                         \
                af[mt][2] = f2tf32(ap[4]);                                    \
                af[mt][3] = f2tf32(ap[8 * A_STRIDE + 4]);                     \
            }                                                                 \
            _Pragma("unroll")                                                 \
            for (int nt = 0; nt < 8; nt++) {                                  \
                int col = nt * 8 + g;                                         \
                uint32_t b0 = __float_as_uint(WS[(ks * 8 + t) * W_STRIDE + col]);     \
                uint32_t b1 = __float_as_uint(WS[(ks * 8 + t + 4) * W_STRIDE + col]); \
                mma_tf32(acc[0][nt], af[0], b0, b1);                          \
                mma_tf32(acc[1][nt], af[1], b0, b1);                          \
            }                                                                 \
        }                                                                     \
    }

            // ---- Layer 1 ----
            GEMM_LAYER(W1_s);
            BAR_SYNC(5, 128);   // consumers done reading A1

            // bias + relu, write u in place (raw float; layer-2 frags re-cvt)
#pragma unroll
            for (int mt = 0; mt < 2; mt++) {
#pragma unroll
                for (int nt = 0; nt < 8; nt++) {
                    int col = nt * 8 + 2 * t;
                    float bc0 = b0_s[col], bc1 = b0_s[col + 1];
                    float* r0 = Aww + (mt * 16 + g) * A_STRIDE + col;
                    float* r1 = Aww + (mt * 16 + g + 8) * A_STRIDE + col;
                    r0[0] = fmaxf(acc[mt][nt][0] + bc0, 0.0f);
                    r0[1] = fmaxf(acc[mt][nt][1] + bc1, 0.0f);
                    r1[0] = fmaxf(acc[mt][nt][2] + bc0, 0.0f);
                    r1[1] = fmaxf(acc[mt][nt][3] + bc1, 0.0f);
                }
            }
            BAR_SYNC(5, 128);   // u complete

            // ---- Layer 2 ----
            GEMM_LAYER(W2_s);

            // ---- epilogue ----
            if (mode == 0) {
                BAR_SYNC(5, 128);                 // all consumers done with A
                if (buf) BAR_ARRIVE(4, 256);      // free buffer for producers
                else     BAR_ARRIVE(3, 256);
#pragma unroll
                for (int mt = 0; mt < 2; mt++) {
                    int node0 = node_base + mw * 32 + mt * 16 + g;
                    int node1 = node0 + 8;
#pragma unroll
                    for (int nt = 0; nt < 8; nt++) {
                        int col = nt * 8 + 2 * t;
                        float bc0 = b1_s[col], bc1 = b1_s[col + 1];
                        if (node0 < N_NODES) {
                            float2 v = make_float2(
                                fmaxf(acc[mt][nt][0] + bc0, 0.0f),
                                fmaxf(acc[mt][nt][1] + bc1, 0.0f));
                            *(float2*)(out + (size_t)node0 * FEAT + col) = v;
                        }
                        if (node1 < N_NODES) {
                            float2 v = make_float2(
                                fmaxf(acc[mt][nt][2] + bc0, 0.0f),
                                fmaxf(acc[mt][nt][3] + bc1, 0.0f));
                            *(float2*)(out + (size_t)node1 * FEAT + col) = v;
                        }
                    }
                }
            } else {
                BAR_SYNC(5, 128);   // all consumers done reading A (layer 2)
#pragma unroll
                for (int mt = 0; mt < 2; mt++) {
#pragma unroll
                    for (int nt = 0; nt < 8; nt++) {
                        int col = nt * 8 + 2 * t;
                        float bc0 = b1_s[col], bc1 = b1_s[col + 1];
                        float* r0 = Aww + (mt * 16 + g) * A_STRIDE + col;
                        float* r1 = Aww + (mt * 16 + g + 8) * A_STRIDE + col;
                        r0[0] = acc[mt][nt][0] + bc0;
                        r0[1] = acc[mt][nt][1] + bc1;
                        r1[0] = acc[mt][nt][2] + bc0;
                        r1[1] = acc[mt][nt][3] + bc1;
                    }
                }
                BAR_SYNC(5, 128);

                // segmented column reduction over sorted batch ids
                int col = tid & 63;
                int half = tid >> 6;     // 0..1, 64 rows each
                int cur = -1;
                float run = 0.0f;
#pragma unroll 8
                for (int r = 0; r < 64; r++) {
                    int rr = half * 64 + r;
                    int b = bat_s[rr];
                    float v = A_s[rr * A_STRIDE + col];
                    if (b != cur) {
                        if (cur >= 0) {
                            float* q = sums + (size_t)cur * FEAT + col;
                            asm volatile("red.global.add.f32 [%0], %1;"
                                         :: "l"(q), "f"(run) : "memory");
                        }
                        cur = b;
                        run = 0.0f;
                    }
                    run += v;
                }
                if (cur >= 0) {
                    float* q = sums + (size_t)cur * FEAT + col;
                    asm volatile("red.global.add.f32 [%0], %1;"
                                 :: "l"(q), "f"(run) : "memory");
                }
                if (buf) BAR_ARRIVE(4, 256);
                else     BAR_ARRIVE(3, 256);
            }
#undef GEMM_LAYER
        }
    }
}

// ---------------------------------------------------------------------------
__global__ __launch_bounds__(64) void classify_kernel(
    const float* __restrict__ sums,
    const float* __restrict__ cnts,
    const float* __restrict__ wc,
    const float* __restrict__ bc,
    float* __restrict__ out)
{
    int g = blockIdx.x;
    int tid = threadIdx.x;
    __shared__ float p[FEAT];
    float cnt = fmaxf(__ldg(cnts + g), 1.0f);
    p[tid] = sums[(size_t)g * FEAT + tid] / cnt;
    __syncthreads();
    if (tid < N_CLS) {
        float acc = bc[tid];
#pragma unroll
        for (int k = 0; k < FEAT; k++) {
            acc = fmaf(p[k], wc[k * N_CLS + tid], acc);
        }
        out[(size_t)g * N_CLS + tid] = acc;
    }
}

// ---------------------------------------------------------------------------
extern "C" void kernel_launch(void* const* d_in, const int* in_sizes, int n_in,
                              void* d_out, int out_size)
{
    const float* x   = (const float*)d_in[0];
    const int*   ei  = (const int*)d_in[1];
    const int*   bat = (const int*)d_in[2];
    const float* w0a = (const float*)d_in[3];
    const float* b0a = (const float*)d_in[4];
    const float* g0  = (const float*)d_in[5];
    const float* be0 = (const float*)d_in[6];
    const float* m0  = (const float*)d_in[7];
    const float* v0  = (const float*)d_in[8];
    const float* w0b = (const float*)d_in[9];
    const float* b0b = (const float*)d_in[10];
    const float* w1a = (const float*)d_in[11];
    const float* b1a = (const float*)d_in[12];
    const float* g1  = (const float*)d_in[13];
    const float* be1 = (const float*)d_in[14];
    const float* m1  = (const float*)d_in[15];
    const float* v1  = (const float*)d_in[16];
    const float* w1b = (const float*)d_in[17];
    const float* b1b = (const float*)d_in[18];
    const float* wc  = (const float*)d_in[19];
    const float* bc  = (const float*)d_in[20];
    float* out = (float*)d_out;

    const int* src = ei;            // edge_index[0]
    const int* dst = ei + N_EDGES;  // edge_index[1]

    float *p_h1, *p_sums, *p_cnts;
    int *p_deg, *p_csr;
    cudaGetSymbolAddress((void**)&p_h1,   g_h1);
    cudaGetSymbolAddress((void**)&p_sums, g_sums);
    cudaGetSymbolAddress((void**)&p_cnts, g_cnts);
    cudaGetSymbolAddress((void**)&p_deg,  g_deg);
    cudaGetSymbolAddress((void**)&p_csr,  g_csr);

    static bool attr_done = false;
    if (!attr_done) {
        cudaFuncSetAttribute(conv_kernel,
                             cudaFuncAttributeMaxDynamicSharedMemorySize,
                             SM_TOTAL);
        attr_done = true;
    }

    const int fill_blocks = (N_EDGES + 255) / 256;   // 3907
    const int node_blocks = (N_NODES + 255) / 256;   // 391

    // ---- CSR build (shared by both convs) ----
    cudaMemsetAsync(p_deg, 0, (size_t)N_NODES * sizeof(int));
    cudaMemsetAsync(p_sums, 0, (size_t)N_GRAPHS * FEAT * sizeof(float));
    cudaMemsetAsync(p_cnts, 0, (size_t)N_GRAPHS * sizeof(float));
    fill_kernel<<<fill_blocks, 256>>>(src, dst, p_deg, p_csr);
    count_kernel<<<node_blocks, 256>>>(bat, p_cnts);

    // ---- Conv 0 (fused gather + MLP) ----
    conv_kernel<<<GRID_CONV, 256, SM_TOTAL>>>(
        x, p_deg, p_csr, w0a, b0a, g0, be0, m0, v0,
        w0b, b0b, p_h1, bat, p_sums, /*mode=*/0);

    // ---- Conv 1 (fused gather + MLP + pooled sum) ----
    conv_kernel<<<GRID_CONV, 256, SM_TOTAL>>>(
        p_h1, p_deg, p_csr, w1a, b1a, g1, be1, m1, v1,
        w1b, b1b, /*out unused*/ p_h1, bat, p_sums, /*mode=*/1);

    // ---- Classify ----
    classify_kernel<<<N_GRAPHS, 64>>>(p_sums, p_cnts, wc, bc, out);
}

// round 11
// speedup vs baseline: 1.0534x; 1.0534x over previous
#include <cuda_runtime.h>
#include <cuda_bf16.h>
#include <math.h>
#include <stdint.h>

#define N_NODES 100000
#define N_EDGES 1000000
#define FEAT 64
#define N_GRAPHS 512
#define N_CLS 10
#define BN_EPS 1e-5f
#define CAP 96

#define NTILES 782
#define NCHUNK 6
#define CHUNK_TILES 131

// Scratch (device globals — no allocation allowed)
__device__ float g_t[N_NODES * FEAT];
__device__ float g_h1[N_NODES * FEAT];
__device__ float g_sums[N_GRAPHS * FEAT];
__device__ float g_cnts[N_GRAPHS];
__device__ int   g_deg[N_NODES];
__device__ int   g_csr[N_NODES * CAP];

// ---------------------------------------------------------------------------
// helpers
// ---------------------------------------------------------------------------
__device__ __forceinline__ uint32_t f2tf32(float x) {
    uint32_t r;
    asm("cvt.rna.tf32.f32 %0, %1;" : "=r"(r) : "f"(x));
    return r;
}

__device__ __forceinline__ void mma_tf32(float* c, const uint32_t* a,
                                         uint32_t b0, uint32_t b1) {
    asm("mma.sync.aligned.m16n8k8.row.col.f32.tf32.tf32.f32 "
        "{%0,%1,%2,%3}, {%4,%5,%6,%7}, {%8,%9}, {%0,%1,%2,%3};"
        : "+f"(c[0]), "+f"(c[1]), "+f"(c[2]), "+f"(c[3])
        : "r"(a[0]), "r"(a[1]), "r"(a[2]), "r"(a[3]), "r"(b0), "r"(b1));
}

// SMEM layout (bytes)
#define A_STRIDE 68
#define W_STRIDE 72
#define SM_A     0
#define SM_W1    34816
#define SM_W2    (SM_W1 + 18432)
#define SM_B0    (SM_W2 + 18432)
#define SM_B1    (SM_B0 + 256)
#define SM_BAT   (SM_B1 + 256)
#define SM_TOTAL (SM_BAT + 512)          // 72704

// ---------------------------------------------------------------------------
// CSR fill: csr[dst*CAP + pos] = src
// ---------------------------------------------------------------------------
__global__ __launch_bounds__(256) void fill_kernel(
    const int* __restrict__ src, const int* __restrict__ dst,
    int* __restrict__ deg, int* __restrict__ csr)
{
    int e = blockIdx.x * blockDim.x + threadIdx.x;
    if (e >= N_EDGES) return;
    int d = __ldg(dst + e);
    int pos = atomicAdd(deg + d, 1);
    if (pos < CAP) csr[d * CAP + pos] = __ldg(src + e);
}

// ---------------------------------------------------------------------------
__global__ __launch_bounds__(256) void count_kernel(
    const int* __restrict__ batch, float* __restrict__ cnts)
{
    int i = blockIdx.x * blockDim.x + threadIdx.x;
    if (i < N_NODES) atomicAdd(cnts + __ldg(batch + i), 1.0f);
}

// ---------------------------------------------------------------------------
// Pull gather over a node range: t[node] = h[node] + sum_{j in csr} h[j]
// 16 threads/node; 4 independent accumulators break the FADD chain.
// ---------------------------------------------------------------------------
__global__ __launch_bounds__(256) void gather_kernel(
    const float* __restrict__ h,
    const int* __restrict__ deg, const int* __restrict__ csr,
    int n_base, int n_cnt,
    float* __restrict__ tout)
{
    int idx = blockIdx.x * blockDim.x + threadIdx.x;
    int local = idx >> 4;
    int c = idx & 15;
    if (local >= n_cnt) return;
    int node = n_base + local;

    int dg = __ldg(deg + node);
    if (dg > CAP) dg = CAP;
    const int* lst = csr + (size_t)node * CAP;

    float4 a0 = __ldg(reinterpret_cast<const float4*>(h + (size_t)node * FEAT) + c);
    float4 a1 = make_float4(0.f, 0.f, 0.f, 0.f);
    float4 a2 = make_float4(0.f, 0.f, 0.f, 0.f);
    float4 a3 = make_float4(0.f, 0.f, 0.f, 0.f);

    int i = 0;
    for (; i + 4 <= dg; i += 4) {
        int s0 = __ldg(lst + i);
        int s1 = __ldg(lst + i + 1);
        int s2 = __ldg(lst + i + 2);
        int s3 = __ldg(lst + i + 3);
        float4 v0 = __ldg(reinterpret_cast<const float4*>(h + (size_t)s0 * FEAT) + c);
        float4 v1 = __ldg(reinterpret_cast<const float4*>(h + (size_t)s1 * FEAT) + c);
        float4 v2 = __ldg(reinterpret_cast<const float4*>(h + (size_t)s2 * FEAT) + c);
        float4 v3 = __ldg(reinterpret_cast<const float4*>(h + (size_t)s3 * FEAT) + c);
        a0.x += v0.x; a0.y += v0.y; a0.z += v0.z; a0.w += v0.w;
        a1.x += v1.x; a1.y += v1.y; a1.z += v1.z; a1.w += v1.w;
        a2.x += v2.x; a2.y += v2.y; a2.z += v2.z; a2.w += v2.w;
        a3.x += v3.x; a3.y += v3.y; a3.z += v3.z; a3.w += v3.w;
    }
    for (; i < dg; i++) {
        int s0 = __ldg(lst + i);
        float4 v = __ldg(reinterpret_cast<const float4*>(h + (size_t)s0 * FEAT) + c);
        a1.x += v.x; a1.y += v.y; a1.z += v.z; a1.w += v.w;
    }
    a0.x += a1.x + a2.x + a3.x;
    a0.y += a1.y + a2.y + a3.y;
    a0.z += a1.z + a2.z + a3.z;
    a0.w += a1.w + a2.w + a3.w;
    *(reinterpret_cast<float4*>(tout + (size_t)node * FEAT) + c) = a0;
}

// ---------------------------------------------------------------------------
// GIN MLP on pre-aggregated t: one 128-node tile per block, 8 warps,
// warp-private 16 rows each (no block sync between layers).
// mode 0: out[node] = relu(mlp(t))
// mode 1: segmented block-reduce mlp(t) rows by sorted batch -> red to sums
// ---------------------------------------------------------------------------
__global__ __launch_bounds__(256) void conv_kernel(
    const float* __restrict__ tin,
    const float* __restrict__ wa, const float* __restrict__ ba,
    const float* __restrict__ gam, const float* __restrict__ bet,
    const float* __restrict__ mu,  const float* __restrict__ var,
    const float* __restrict__ wb,  const float* __restrict__ bb,
    float* __restrict__ out, const int* __restrict__ batch,
    float* __restrict__ sums, int mode, int tile_base)
{
    extern __shared__ __align__(16) char sm[];
    float* A_s  = (float*)(sm + SM_A);
    float* W1_s = (float*)(sm + SM_W1);
    float* W2_s = (float*)(sm + SM_W2);
    float* b0_s = (float*)(sm + SM_B0);
    float* b1_s = (float*)(sm + SM_B1);
    int*   bat_s = (int*)(sm + SM_BAT);

    int tid = threadIdx.x;
    int wid = tid >> 5;
    int lane = tid & 31;
    int g = lane >> 2;
    int t = lane & 3;
    int tile = tile_base + blockIdx.x;
    int node_base = tile * 128;

    // ---- stage A tile via cp.async (2 threads/row, 32 floats each) ----
    {
        int row = tid >> 1, half = tid & 1;
        int node = node_base + row;
        uint32_t dst = (uint32_t)__cvta_generic_to_shared(
            A_s + row * A_STRIDE + half * 32);
        if (node < N_NODES) {
            const float* src = tin + (size_t)node * FEAT + half * 32;
#pragma unroll
            for (int q = 0; q < 8; q++)
                asm volatile("cp.async.cg.shared.global [%0], [%1], 16;"
                             :: "r"(dst + q * 16), "l"(src + q * 4) : "memory");
        } else {
#pragma unroll
            for (int q = 0; q < 8; q++)
                asm volatile("st.shared.v4.b32 [%0], {%1,%1,%1,%1};"
                             :: "r"(dst + q * 16), "r"(0u) : "memory");
        }
        if (half == 0)
            bat_s[row] = (node < N_NODES) ? __ldg(batch + node) : -1;
        asm volatile("cp.async.commit_group;" ::: "memory");
    }

    // ---- stage weights (BN folded into W1), tf32-rounded ----
    for (int i = tid; i < FEAT * FEAT; i += 256) {
        int n = i & 63;
        float s = __ldg(gam + n) * rsqrtf(__ldg(var + n) + BN_EPS);
        W1_s[(i >> 6) * W_STRIDE + n] = __uint_as_float(f2tf32(__ldg(wa + i) * s));
        W2_s[(i >> 6) * W_STRIDE + n] = __uint_as_float(f2tf32(__ldg(wb + i)));
    }
    if (tid < FEAT) {
        float s = __ldg(gam + tid) * rsqrtf(__ldg(var + tid) + BN_EPS);
        b0_s[tid] = (__ldg(ba + tid) - __ldg(mu + tid)) * s + __ldg(bet + tid);
        b1_s[tid] = __ldg(bb + tid);
    }
    asm volatile("cp.async.wait_group 0;" ::: "memory");
    __syncthreads();

    const float* Aw = A_s + (wid * 16) * A_STRIDE;
    float* Aww = A_s + (wid * 16) * A_STRIDE;

    float acc[8][4];

#define GEMM_LAYER(WS)                                                       \
    {                                                                        \
        _Pragma("unroll")                                                    \
        for (int nt = 0; nt < 8; nt++)                                       \
            _Pragma("unroll")                                                \
            for (int e = 0; e < 4; e++) acc[nt][e] = 0.0f;                   \
        _Pragma("unroll")                                                    \
        for (int ks = 0; ks < 8; ks++) {                                     \
            uint32_t af[4];                                                  \
            const float* ap = Aw + g * A_STRIDE + ks * 8 + t;                \
            af[0] = f2tf32(ap[0]);                                           \
            af[1] = f2tf32(ap[8 * A_STRIDE]);                                \
            af[2] = f2tf32(ap[4]);                                           \
            af[3] = f2tf32(ap[8 * A_STRIDE + 4]);                            \
            _Pragma("unroll")                                                \
            for (int nt = 0; nt < 8; nt++) {                                 \
                int col = nt * 8 + g;                                        \
                uint32_t b0 = __float_as_uint(WS[(ks * 8 + t) * W_STRIDE + col]);     \
                uint32_t b1 = __float_as_uint(WS[(ks * 8 + t + 4) * W_STRIDE + col]); \
                mma_tf32(acc[nt], af, b0, b1);                               \
            }                                                                \
        }                                                                    \
    }

    // ---- Layer 1 ----
    GEMM_LAYER(W1_s);

    // bias + relu, write u into own rows (warp-private -> syncwarp only)
#pragma unroll
    for (int nt = 0; nt < 8; nt++) {
        int col = nt * 8 + 2 * t;
        float bc0 = b0_s[col], bc1 = b0_s[col + 1];
        float* r0 = Aww + g * A_STRIDE + col;
        float* r1 = Aww + (g + 8) * A_STRIDE + col;
        r0[0] = fmaxf(acc[nt][0] + bc0, 0.0f);
        r0[1] = fmaxf(acc[nt][1] + bc1, 0.0f);
        r1[0] = fmaxf(acc[nt][2] + bc0, 0.0f);
        r1[1] = fmaxf(acc[nt][3] + bc1, 0.0f);
    }
    __syncwarp();

    // ---- Layer 2 ----
    GEMM_LAYER(W2_s);

    // ---- epilogue ----
    if (mode == 0) {
        int node0 = node_base + wid * 16 + g;
        int node1 = node0 + 8;
#pragma unroll
        for (int nt = 0; nt < 8; nt++) {
            int col = nt * 8 + 2 * t;
            float bc0 = b1_s[col], bc1 = b1_s[col + 1];
            if (node0 < N_NODES) {
                float2 v = make_float2(fmaxf(acc[nt][0] + bc0, 0.0f),
                                       fmaxf(acc[nt][1] + bc1, 0.0f));
                *(float2*)(out + (size_t)node0 * FEAT + col) = v;
            }
            if (node1 < N_NODES) {
                float2 v = make_float2(fmaxf(acc[nt][2] + bc0, 0.0f),
                                       fmaxf(acc[nt][3] + bc1, 0.0f));
                *(float2*)(out + (size_t)node1 * FEAT + col) = v;
            }
        }
    } else {
        // write y (bias, no relu) into own rows, then block-wide reduce
#pragma unroll
        for (int nt = 0; nt < 8; nt++) {
            int col = nt * 8 + 2 * t;
            float bc0 = b1_s[col], bc1 = b1_s[col + 1];
            float* r0 = Aww + g * A_STRIDE + col;
            float* r1 = Aww + (g + 8) * A_STRIDE + col;
            r0[0] = acc[nt][0] + bc0;
            r0[1] = acc[nt][1] + bc1;
            r1[0] = acc[nt][2] + bc0;
            r1[1] = acc[nt][3] + bc1;
        }
        __syncthreads();

        // segmented column reduction over sorted batch ids
        int col = tid & 63;
        int quarter = tid >> 6;       // 0..3, 32 rows each
        int cur = -1;
        float run = 0.0f;
#pragma unroll 8
        for (int r = 0; r < 32; r++) {
            int rr = quarter * 32 + r;
            int b = bat_s[rr];
            float v = A_s[rr * A_STRIDE + col];
            if (b != cur) {
                if (cur >= 0) {
                    float* q = sums + (size_t)cur * FEAT + col;
                    asm volatile("red.global.add.f32 [%0], %1;"
                                 :: "l"(q), "f"(run) : "memory");
                }
                cur = b;
                run = 0.0f;
            }
            run += v;
        }
        if (cur >= 0) {
            float* q = sums + (size_t)cur * FEAT + col;
            asm volatile("red.global.add.f32 [%0], %1;"
                         :: "l"(q), "f"(run) : "memory");
        }
    }
#undef GEMM_LAYER
}

// ---------------------------------------------------------------------------
__global__ __launch_bounds__(64) void classify_kernel(
    const float* __restrict__ sums,
    const float* __restrict__ cnts,
    const float* __restrict__ wc,
    const float* __restrict__ bc,
    float* __restrict__ out)
{
    int g = blockIdx.x;
    int tid = threadIdx.x;
    __shared__ float p[FEAT];
    float cnt = fmaxf(__ldg(cnts + g), 1.0f);
    p[tid] = sums[(size_t)g * FEAT + tid] / cnt;
    __syncthreads();
    if (tid < N_CLS) {
        float acc = bc[tid];
#pragma unroll
        for (int k = 0; k < FEAT; k++) {
            acc = fmaf(p[k], wc[k * N_CLS + tid], acc);
        }
        out[(size_t)g * N_CLS + tid] = acc;
    }
}

// ---------------------------------------------------------------------------
extern "C" void kernel_launch(void* const* d_in, const int* in_sizes, int n_in,
                              void* d_out, int out_size)
{
    const float* x   = (const float*)d_in[0];
    const int*   ei  = (const int*)d_in[1];
    const int*   bat = (const int*)d_in[2];
    const float* w0a = (const float*)d_in[3];
    const float* b0a = (const float*)d_in[4];
    const float* g0  = (const float*)d_in[5];
    const float* be0 = (const float*)d_in[6];
    const float* m0  = (const float*)d_in[7];
    const float* v0  = (const float*)d_in[8];
    const float* w0b = (const float*)d_in[9];
    const float* b0b = (const float*)d_in[10];
    const float* w1a = (const float*)d_in[11];
    const float* b1a = (const float*)d_in[12];
    const float* g1  = (const float*)d_in[13];
    const float* be1 = (const float*)d_in[14];
    const float* m1  = (const float*)d_in[15];
    const float* v1  = (const float*)d_in[16];
    const float* w1b = (const float*)d_in[17];
    const float* b1b = (const float*)d_in[18];
    const float* wc  = (const float*)d_in[19];
    const float* bc  = (const float*)d_in[20];
    float* out = (float*)d_out;

    const int* src = ei;            // edge_index[0]
    const int* dst = ei + N_EDGES;  // edge_index[1]

    float *p_t, *p_h1, *p_sums, *p_cnts;
    int *p_deg, *p_csr;
    cudaGetSymbolAddress((void**)&p_t,    g_t);
    cudaGetSymbolAddress((void**)&p_h1,   g_h1);
    cudaGetSymbolAddress((void**)&p_sums, g_sums);
    cudaGetSymbolAddress((void**)&p_cnts, g_cnts);
    cudaGetSymbolAddress((void**)&p_deg,  g_deg);
    cudaGetSymbolAddress((void**)&p_csr,  g_csr);

    // one-time setup: smem attr + side stream + events (fallback: serial)
    static int inited = 0;
    static int use_streams = 0;
    static cudaStream_t sG = 0;
    static cudaEvent_t ev[NCHUNK * 2 + 2];
    if (!inited) {
        inited = 1;
        cudaFuncSetAttribute(conv_kernel,
                             cudaFuncAttributeMaxDynamicSharedMemorySize,
                             SM_TOTAL);
        use_streams = (cudaStreamCreateWithFlags(&sG, cudaStreamNonBlocking)
                       == cudaSuccess);
        for (int i = 0; i < NCHUNK * 2 + 2 && use_streams; i++)
            use_streams = (cudaEventCreateWithFlags(&ev[i],
                               cudaEventDisableTiming) == cudaSuccess);
        if (!use_streams) sG = 0;
    }
    cudaStream_t s0 = 0;

    const int fill_blocks = (N_EDGES + 255) / 256;
    const int node_blocks = (N_NODES + 255) / 256;

    // ---- preamble on main stream ----
    cudaMemsetAsync(p_deg, 0, (size_t)N_NODES * sizeof(int), s0);
    cudaMemsetAsync(p_sums, 0, (size_t)N_GRAPHS * FEAT * sizeof(float), s0);
    cudaMemsetAsync(p_cnts, 0, (size_t)N_GRAPHS * sizeof(float), s0);
    fill_kernel<<<fill_blocks, 256, 0, s0>>>(src, dst, p_deg, p_csr);
    count_kernel<<<node_blocks, 256, 0, s0>>>(bat, p_cnts);
    if (use_streams) {
        cudaEventRecord(ev[2 * NCHUNK], s0);
        cudaStreamWaitEvent(sG, ev[2 * NCHUNK], 0);
    }

    // ---- two layers, chunk-pipelined across streams ----
    for (int layer = 0; layer < 2; layer++) {
        const float* hin = (layer == 0) ? x : p_h1;
        const float* wa = (layer == 0) ? w0a : w1a;
        const float* ba = (layer == 0) ? b0a : b1a;
        const float* ga = (layer == 0) ? g0 : g1;
        const float* be = (layer == 0) ? be0 : be1;
        const float* mu = (layer == 0) ? m0 : m1;
        const float* va = (layer == 0) ? v0 : v1;
        const float* wb = (layer == 0) ? w0b : w1b;
        const float* bb = (layer == 0) ? b0b : b1b;
        int mode = layer;

        int tile_base = 0;
        for (int j = 0; j < NCHUNK; j++) {
            int tiles = (j == NCHUNK - 1) ? (NTILES - tile_base) : CHUNK_TILES;
            int n_base = tile_base * 128;
            int n_cnt = N_NODES - n_base;
            if (n_cnt > tiles * 128) n_cnt = tiles * 128;
            int gblocks = (n_cnt * 16 + 255) / 256;

            gather_kernel<<<gblocks, 256, 0, sG>>>(
                hin, p_deg, p_csr, n_base, n_cnt, p_t);
            if (use_streams) {
                cudaEventRecord(ev[layer * NCHUNK + j], sG);
                cudaStreamWaitEvent(s0, ev[layer * NCHUNK + j], 0);
            }
            conv_kernel<<<tiles, 256, SM_TOTAL, s0>>>(
                p_t, wa, ba, ga, be, mu, va, wb, bb,
                p_h1, bat, p_sums, mode, tile_base);
            tile_base += tiles;
        }
        if (layer == 0 && use_streams) {
            // h1 complete on s0; layer-1 gathers must wait for it
            cudaEventRecord(ev[2 * NCHUNK + 1], s0);
            cudaStreamWaitEvent(sG, ev[2 * NCHUNK + 1], 0);
        }
    }

    // ---- Classify (main stream, after all conv1 chunks) ----
    classify_kernel<<<N_GRAPHS, 64, 0, s0>>>(p_sums, p_cnts, wc, bc, out);
}

// round 12
// speedup vs baseline: 1.5827x; 1.5025x over previous
#include <cuda_runtime.h>
#include <cuda_bf16.h>
#include <math.h>
#include <stdint.h>

#define N_NODES 100000
#define N_EDGES 1000000
#define FEAT 64
#define N_GRAPHS 512
#define N_CLS 10
#define BN_EPS 1e-5f
#define CAP 96

#define NTILES 782
#define GRID_CONV 444

// Scratch (device globals — no allocation allowed)
__device__ float g_h1[N_NODES * FEAT];
__device__ float g_sums[N_GRAPHS * FEAT];
__device__ float g_cnts[N_GRAPHS];
__device__ int   g_deg[N_NODES];
__device__ int   g_csr[N_NODES * CAP];

// ---------------------------------------------------------------------------
// helpers
// ---------------------------------------------------------------------------
__device__ __forceinline__ uint32_t f2tf32(float x) {
    uint32_t r;
    asm("cvt.rna.tf32.f32 %0, %1;" : "=r"(r) : "f"(x));
    return r;
}

__device__ __forceinline__ void mma_tf32(float* c, const uint32_t* a,
                                         uint32_t b0, uint32_t b1) {
    asm("mma.sync.aligned.m16n8k8.row.col.f32.tf32.tf32.f32 "
        "{%0,%1,%2,%3}, {%4,%5,%6,%7}, {%8,%9}, {%0,%1,%2,%3};"
        : "+f"(c[0]), "+f"(c[1]), "+f"(c[2]), "+f"(c[3])
        : "r"(a[0]), "r"(a[1]), "r"(a[2]), "r"(a[3]), "r"(b0), "r"(b1));
}

// SMEM layout (bytes)
#define A_STRIDE 68
#define W_STRIDE 72
#define SM_A     0
#define SM_W1    34816
#define SM_W2    (SM_W1 + 18432)
#define SM_B0    (SM_W2 + 18432)
#define SM_B1    (SM_B0 + 256)
#define SM_BAT   (SM_B1 + 256)
#define SM_TOTAL (SM_BAT + 512)          // 72704 bytes -> 3 blocks/SM

// ---------------------------------------------------------------------------
// CSR fill: csr[dst*CAP + pos] = src
// ---------------------------------------------------------------------------
__global__ __launch_bounds__(256) void fill_kernel(
    const int* __restrict__ src, const int* __restrict__ dst,
    int* __restrict__ deg, int* __restrict__ csr)
{
    int e = blockIdx.x * blockDim.x + threadIdx.x;
    if (e >= N_EDGES) return;
    int d = __ldg(dst + e);
    int pos = atomicAdd(deg + d, 1);
    if (pos < CAP) csr[d * CAP + pos] = __ldg(src + e);
}

// ---------------------------------------------------------------------------
__global__ __launch_bounds__(256) void count_kernel(
    const int* __restrict__ batch, float* __restrict__ cnts)
{
    int i = blockIdx.x * blockDim.x + threadIdx.x;
    if (i < N_NODES) atomicAdd(cnts + __ldg(batch + i), 1.0f);
}

// ---------------------------------------------------------------------------
// Fused gather + GIN MLP, persistent, all-warp phases.
// Per tile: ALL 256 threads gather t = h[node] + sum h[nbr] straight into
// SMEM (16 threads/node), then 8-warp split tf32 GEMM (4 row x 2 col groups).
// mode 0: out[node] = relu(mlp(t))
// mode 1: segmented block-reduce mlp(t) rows by sorted batch -> red to sums
// ---------------------------------------------------------------------------
__global__ __launch_bounds__(256, 3) void conv_kernel(
    const float* __restrict__ h,
    const int* __restrict__ deg, const int* __restrict__ csr,
    const float* __restrict__ wa, const float* __restrict__ ba,
    const float* __restrict__ gam, const float* __restrict__ bet,
    const float* __restrict__ mu,  const float* __restrict__ var,
    const float* __restrict__ wb,  const float* __restrict__ bb,
    float* __restrict__ out, const int* __restrict__ batch,
    float* __restrict__ sums, int mode)
{
    extern __shared__ __align__(16) char sm[];
    float* A_s  = (float*)(sm + SM_A);
    float* W1_s = (float*)(sm + SM_W1);
    float* W2_s = (float*)(sm + SM_W2);
    float* b0_s = (float*)(sm + SM_B0);
    float* b1_s = (float*)(sm + SM_B1);
    int*   bat_s = (int*)(sm + SM_BAT);

    int tid = threadIdx.x;
    int wid = tid >> 5;
    int lane = tid & 31;
    int g = lane >> 2;
    int t = lane & 3;
    int mw = wid & 3;                 // row group (32 rows)
    int ncol0 = (wid >> 2) * 32;      // column base (32 cols)
    int prow = tid >> 4;              // gather: node slot (0..15)
    int pc = tid & 15;                // gather: float4 column

    // stage weights once per block (BN folded into W1), tf32-rounded
    for (int i = tid; i < FEAT * FEAT; i += 256) {
        int n = i & 63;
        float s = __ldg(gam + n) * rsqrtf(__ldg(var + n) + BN_EPS);
        W1_s[(i >> 6) * W_STRIDE + n] = __uint_as_float(f2tf32(__ldg(wa + i) * s));
        W2_s[(i >> 6) * W_STRIDE + n] = __uint_as_float(f2tf32(__ldg(wb + i)));
    }
    if (tid < FEAT) {
        float s = __ldg(gam + tid) * rsqrtf(__ldg(var + tid) + BN_EPS);
        b0_s[tid] = (__ldg(ba + tid) - __ldg(mu + tid)) * s + __ldg(bet + tid);
        b1_s[tid] = __ldg(bb + tid);
    }
    // visibility of W covered by the gather->GEMM sync inside the loop

    for (int tile = blockIdx.x; tile < NTILES; tile += GRID_CONV) {
        int node_base = tile * 128;

        // ============ gather phase: all 8 warps, 16 nodes/pass ============
        for (int s = 0; s < 8; s++) {
            int row = s * 16 + prow;
            int node = node_base + row;
            float4 a0 = make_float4(0.f, 0.f, 0.f, 0.f);
            float4 a1 = make_float4(0.f, 0.f, 0.f, 0.f);
            float4 a2 = make_float4(0.f, 0.f, 0.f, 0.f);
            float4 a3 = make_float4(0.f, 0.f, 0.f, 0.f);
            if (node < N_NODES) {
                a0 = __ldg(reinterpret_cast<const float4*>(
                        h + (size_t)node * FEAT) + pc);
                int dg = __ldg(deg + node);
                if (dg > CAP) dg = CAP;
                const int* lst = csr + (size_t)node * CAP;
                int i = 0;
                for (; i + 4 <= dg; i += 4) {
                    int s0 = __ldg(lst + i);
                    int s1 = __ldg(lst + i + 1);
                    int s2 = __ldg(lst + i + 2);
                    int s3 = __ldg(lst + i + 3);
                    float4 v0 = __ldg(reinterpret_cast<const float4*>(h + (size_t)s0 * FEAT) + pc);
                    float4 v1 = __ldg(reinterpret_cast<const float4*>(h + (size_t)s1 * FEAT) + pc);
                    float4 v2 = __ldg(reinterpret_cast<const float4*>(h + (size_t)s2 * FEAT) + pc);
                    float4 v3 = __ldg(reinterpret_cast<const float4*>(h + (size_t)s3 * FEAT) + pc);
                    a0.x += v0.x; a0.y += v0.y; a0.z += v0.z; a0.w += v0.w;
                    a1.x += v1.x; a1.y += v1.y; a1.z += v1.z; a1.w += v1.w;
                    a2.x += v2.x; a2.y += v2.y; a2.z += v2.z; a2.w += v2.w;
                    a3.x += v3.x; a3.y += v3.y; a3.z += v3.z; a3.w += v3.w;
                }
                for (; i < dg; i++) {
                    int s0 = __ldg(lst + i);
                    float4 v = __ldg(reinterpret_cast<const float4*>(h + (size_t)s0 * FEAT) + pc);
                    a1.x += v.x; a1.y += v.y; a1.z += v.z; a1.w += v.w;
                }
            }
            a0.x += a1.x + a2.x + a3.x;
            a0.y += a1.y + a2.y + a3.y;
            a0.z += a1.z + a2.z + a3.z;
            a0.w += a1.w + a2.w + a3.w;
            *reinterpret_cast<float4*>(A_s + row * A_STRIDE + pc * 4) = a0;
            if (pc == 0)
                bat_s[row] = (node < N_NODES) ? __ldg(batch + node) : -1;
        }
        __syncthreads();   // tile gathered (also orders weight staging)

        // ============ GEMM phase ============
        const float* Aw = A_s + (mw * 32) * A_STRIDE;
        float* Aww = A_s + (mw * 32) * A_STRIDE;

        float acc[2][4][4];

#define GEMM_LAYER(WS)                                                        \
    {                                                                         \
        _Pragma("unroll")                                                     \
        for (int mt = 0; mt < 2; mt++)                                        \
            _Pragma("unroll")                                                 \
            for (int nt = 0; nt < 4; nt++)                                    \
                _Pragma("unroll")                                             \
                for (int e = 0; e < 4; e++) acc[mt][nt][e] = 0.0f;            \
        _Pragma("unroll")                                                     \
        for (int ks = 0; ks < 8; ks++) {                                      \
            uint32_t af[2][4];                                                \
            _Pragma("unroll")                                                 \
            for (int mt = 0; mt < 2; mt++) {                                  \
                const float* ap = Aw + (mt * 16 + g) * A_STRIDE + ks * 8 + t; \
                af[mt][0] = f2tf32(ap[0]);                                    \
                af[mt][1] = f2tf32(ap[8 * A_STRIDE]);                         \
                af[mt][2] = f2tf32(ap[4]);                                    \
                af[mt][3] = f2tf32(ap[8 * A_STRIDE + 4]);                     \
            }                                                                 \
            _Pragma("unroll")                                                 \
            for (int nt = 0; nt < 4; nt++) {                                  \
                int col = ncol0 + nt * 8 + g;                                 \
                uint32_t b0 = __float_as_uint(WS[(ks * 8 + t) * W_STRIDE + col]);     \
                uint32_t b1 = __float_as_uint(WS[(ks * 8 + t + 4) * W_STRIDE + col]); \
                mma_tf32(acc[0][nt], af[0], b0, b1);                          \
                mma_tf32(acc[1][nt], af[1], b0, b1);                          \
            }                                                                 \
        }                                                                     \
    }

        // ---- Layer 1 ----
        GEMM_LAYER(W1_s);
        __syncthreads();   // all warps done reading A1

        // bias + relu, write u in place
#pragma unroll
        for (int mt = 0; mt < 2; mt++) {
#pragma unroll
            for (int nt = 0; nt < 4; nt++) {
                int col = ncol0 + nt * 8 + 2 * t;
                float bc0 = b0_s[col], bc1 = b0_s[col + 1];
                float* r0 = Aww + (mt * 16 + g) * A_STRIDE + col;
                float* r1 = Aww + (mt * 16 + g + 8) * A_STRIDE + col;
                r0[0] = fmaxf(acc[mt][nt][0] + bc0, 0.0f);
                r0[1] = fmaxf(acc[mt][nt][1] + bc1, 0.0f);
                r1[0] = fmaxf(acc[mt][nt][2] + bc0, 0.0f);
                r1[1] = fmaxf(acc[mt][nt][3] + bc1, 0.0f);
            }
        }
        __syncthreads();   // u complete

        // ---- Layer 2 ----
        GEMM_LAYER(W2_s);

        // ---- epilogue ----
        if (mode == 0) {
#pragma unroll
            for (int mt = 0; mt < 2; mt++) {
                int node0 = node_base + mw * 32 + mt * 16 + g;
                int node1 = node0 + 8;
#pragma unroll
                for (int nt = 0; nt < 4; nt++) {
                    int col = ncol0 + nt * 8 + 2 * t;
                    float bc0 = b1_s[col], bc1 = b1_s[col + 1];
                    if (node0 < N_NODES) {
                        float2 v = make_float2(fmaxf(acc[mt][nt][0] + bc0, 0.0f),
                                               fmaxf(acc[mt][nt][1] + bc1, 0.0f));
                        *(float2*)(out + (size_t)node0 * FEAT + col) = v;
                    }
                    if (node1 < N_NODES) {
                        float2 v = make_float2(fmaxf(acc[mt][nt][2] + bc0, 0.0f),
                                               fmaxf(acc[mt][nt][3] + bc1, 0.0f));
                        *(float2*)(out + (size_t)node1 * FEAT + col) = v;
                    }
                }
            }
        } else {
            __syncthreads();   // all warps done reading A (layer 2)
#pragma unroll
            for (int mt = 0; mt < 2; mt++) {
#pragma unroll
                for (int nt = 0; nt < 4; nt++) {
                    int col = ncol0 + nt * 8 + 2 * t;
                    float bc0 = b1_s[col], bc1 = b1_s[col + 1];
                    float* r0 = Aww + (mt * 16 + g) * A_STRIDE + col;
                    float* r1 = Aww + (mt * 16 + g + 8) * A_STRIDE + col;
                    r0[0] = acc[mt][nt][0] + bc0;
                    r0[1] = acc[mt][nt][1] + bc1;
                    r1[0] = acc[mt][nt][2] + bc0;
                    r1[1] = acc[mt][nt][3] + bc1;
                }
            }
            __syncthreads();

            // segmented column reduction over sorted batch ids
            int col = tid & 63;
            int quarter = tid >> 6;       // 0..3, 32 rows each
            int cur = -1;
            float run = 0.0f;
#pragma unroll 8
            for (int r = 0; r < 32; r++) {
                int rr = quarter * 32 + r;
                int b = bat_s[rr];
                float v = A_s[rr * A_STRIDE + col];
                if (b != cur) {
                    if (cur >= 0) {
                        float* q = sums + (size_t)cur * FEAT + col;
                        asm volatile("red.global.add.f32 [%0], %1;"
                                     :: "l"(q), "f"(run) : "memory");
                    }
                    cur = b;
                    run = 0.0f;
                }
                run += v;
            }
            if (cur >= 0) {
                float* q = sums + (size_t)cur * FEAT + col;
                asm volatile("red.global.add.f32 [%0], %1;"
                             :: "l"(q), "f"(run) : "memory");
            }
        }
        __syncthreads();   // done with A before next tile's gather
#undef GEMM_LAYER
    }
}

// ---------------------------------------------------------------------------
__global__ __launch_bounds__(64) void classify_kernel(
    const float* __restrict__ sums,
    const float* __restrict__ cnts,
    const float* __restrict__ wc,
    const float* __restrict__ bc,
    float* __restrict__ out)
{
    int g = blockIdx.x;
    int tid = threadIdx.x;
    __shared__ float p[FEAT];
    float cnt = fmaxf(__ldg(cnts + g), 1.0f);
    p[tid] = sums[(size_t)g * FEAT + tid] / cnt;
    __syncthreads();
    if (tid < N_CLS) {
        float acc = bc[tid];
#pragma unroll
        for (int k = 0; k < FEAT; k++) {
            acc = fmaf(p[k], wc[k * N_CLS + tid], acc);
        }
        out[(size_t)g * N_CLS + tid] = acc;
    }
}

// ---------------------------------------------------------------------------
extern "C" void kernel_launch(void* const* d_in, const int* in_sizes, int n_in,
                              void* d_out, int out_size)
{
    const float* x   = (const float*)d_in[0];
    const int*   ei  = (const int*)d_in[1];
    const int*   bat = (const int*)d_in[2];
    const float* w0a = (const float*)d_in[3];
    const float* b0a = (const float*)d_in[4];
    const float* g0  = (const float*)d_in[5];
    const float* be0 = (const float*)d_in[6];
    const float* m0  = (const float*)d_in[7];
    const float* v0  = (const float*)d_in[8];
    const float* w0b = (const float*)d_in[9];
    const float* b0b = (const float*)d_in[10];
    const float* w1a = (const float*)d_in[11];
    const float* b1a = (const float*)d_in[12];
    const float* g1  = (const float*)d_in[13];
    const float* be1 = (const float*)d_in[14];
    const float* m1  = (const float*)d_in[15];
    const float* v1  = (const float*)d_in[16];
    const float* w1b = (const float*)d_in[17];
    const float* b1b = (const float*)d_in[18];
    const float* wc  = (const float*)d_in[19];
    const float* bc  = (const float*)d_in[20];
    float* out = (float*)d_out;

    const int* src = ei;            // edge_index[0]
    const int* dst = ei + N_EDGES;  // edge_index[1]

    float *p_h1, *p_sums, *p_cnts;
    int *p_deg, *p_csr;
    cudaGetSymbolAddress((void**)&p_h1,   g_h1);
    cudaGetSymbolAddress((void**)&p_sums, g_sums);
    cudaGetSymbolAddress((void**)&p_cnts, g_cnts);
    cudaGetSymbolAddress((void**)&p_deg,  g_deg);
    cudaGetSymbolAddress((void**)&p_csr,  g_csr);

    static bool attr_done = false;
    if (!attr_done) {
        cudaFuncSetAttribute(conv_kernel,
                             cudaFuncAttributeMaxDynamicSharedMemorySize,
                             SM_TOTAL);
        attr_done = true;
    }

    const int fill_blocks = (N_EDGES + 255) / 256;
    const int node_blocks = (N_NODES + 255) / 256;

    // ---- CSR build + pool init ----
    cudaMemsetAsync(p_deg, 0, (size_t)N_NODES * sizeof(int));
    cudaMemsetAsync(p_sums, 0, (size_t)N_GRAPHS * FEAT * sizeof(float));
    cudaMemsetAsync(p_cnts, 0, (size_t)N_GRAPHS * sizeof(float));
    fill_kernel<<<fill_blocks, 256>>>(src, dst, p_deg, p_csr);
    count_kernel<<<node_blocks, 256>>>(bat, p_cnts);

    // ---- Conv 0 (fused gather + MLP) ----
    conv_kernel<<<GRID_CONV, 256, SM_TOTAL>>>(
        x, p_deg, p_csr, w0a, b0a, g0, be0, m0, v0,
        w0b, b0b, p_h1, bat, p_sums, /*mode=*/0);

    // ---- Conv 1 (fused gather + MLP + pooled sum) ----
    conv_kernel<<<GRID_CONV, 256, SM_TOTAL>>>(
        p_h1, p_deg, p_csr, w1a, b1a, g1, be1, m1, v1,
        w1b, b1b, /*out unused*/ p_h1, bat, p_sums, /*mode=*/1);

    // ---- Classify ----
    classify_kernel<<<N_GRAPHS, 64>>>(p_sums, p_cnts, wc, bc, out);
}

// round 13
// speedup vs baseline: 1.8085x; 1.1426x over previous
#include <cuda_runtime.h>
#include <cuda_bf16.h>
#include <math.h>
#include <stdint.h>

#define N_NODES 100000
#define N_EDGES 1000000
#define FEAT 64
#define N_GRAPHS 512
#define N_CLS 10
#define BN_EPS 1e-5f
#define CAP 96

#define NTILES 782
#define GRID_CONV 444

// Scratch (device globals — no allocation allowed)
__device__ float g_h1[N_NODES * FEAT];
__device__ float g_sums[N_GRAPHS * FEAT];
__device__ float g_cnts[N_GRAPHS];
__device__ int   g_deg[N_NODES];
__device__ int   g_csr[N_NODES * CAP];

// ---------------------------------------------------------------------------
// helpers
// ---------------------------------------------------------------------------
__device__ __forceinline__ uint32_t f2tf32(float x) {
    uint32_t r;
    asm("cvt.rna.tf32.f32 %0, %1;" : "=r"(r) : "f"(x));
    return r;
}

__device__ __forceinline__ void mma_tf32(float* c, const uint32_t* a,
                                         uint32_t b0, uint32_t b1) {
    asm("mma.sync.aligned.m16n8k8.row.col.f32.tf32.tf32.f32 "
        "{%0,%1,%2,%3}, {%4,%5,%6,%7}, {%8,%9}, {%0,%1,%2,%3};"
        : "+f"(c[0]), "+f"(c[1]), "+f"(c[2]), "+f"(c[3])
        : "r"(a[0]), "r"(a[1]), "r"(a[2]), "r"(a[3]), "r"(b0), "r"(b1));
}

__device__ __forceinline__ void fma4(float4& a, float m, const float4& v) {
    a.x = fmaf(m, v.x, a.x);
    a.y = fmaf(m, v.y, a.y);
    a.z = fmaf(m, v.z, a.z);
    a.w = fmaf(m, v.w, a.w);
}
__device__ __forceinline__ void add4(float4& a, const float4& v) {
    a.x += v.x; a.y += v.y; a.z += v.z; a.w += v.w;
}

// SMEM layout (bytes)
#define A_STRIDE 68
#define W_STRIDE 72
#define SM_A     0
#define SM_W1    34816
#define SM_W2    (SM_W1 + 18432)
#define SM_B0    (SM_W2 + 18432)
#define SM_B1    (SM_B0 + 256)
#define SM_BAT   (SM_B1 + 256)
#define SM_TOTAL (SM_BAT + 512)          // 72704 bytes -> 3 blocks/SM

// ---------------------------------------------------------------------------
// CSR fill: csr[dst*CAP + pos] = src
// ---------------------------------------------------------------------------
__global__ __launch_bounds__(256) void fill_kernel(
    const int* __restrict__ src, const int* __restrict__ dst,
    int* __restrict__ deg, int* __restrict__ csr)
{
    int e = blockIdx.x * blockDim.x + threadIdx.x;
    if (e >= N_EDGES) return;
    int d = __ldg(dst + e);
    int pos = atomicAdd(deg + d, 1);
    if (pos < CAP) csr[d * CAP + pos] = __ldg(src + e);
}

// ---------------------------------------------------------------------------
__global__ __launch_bounds__(256) void count_kernel(
    const int* __restrict__ batch, float* __restrict__ cnts)
{
    int i = blockIdx.x * blockDim.x + threadIdx.x;
    if (i < N_NODES) atomicAdd(cnts + __ldg(batch + i), 1.0f);
}

// ---------------------------------------------------------------------------
// Fused gather + GIN MLP, persistent, all-warp phases.
// Gather: 8 threads/node (two float4 slices each), 32 nodes/pass, 4 passes,
//   4-edge unroll with clamp+mask remainder -> 8 independent gathers in flight.
// GEMM: 8-warp split tf32 (4 row x 2 col groups).
// mode 0: out[node] = relu(mlp(t))
// mode 1: segmented block-reduce mlp(t) rows by sorted batch -> red to sums
// ---------------------------------------------------------------------------
__global__ __launch_bounds__(256, 3) void conv_kernel(
    const float* __restrict__ h,
    const int* __restrict__ deg, const int* __restrict__ csr,
    const float* __restrict__ wa, const float* __restrict__ ba,
    const float* __restrict__ gam, const float* __restrict__ bet,
    const float* __restrict__ mu,  const float* __restrict__ var,
    const float* __restrict__ wb,  const float* __restrict__ bb,
    float* __restrict__ out, const int* __restrict__ batch,
    float* __restrict__ sums, int mode)
{
    extern __shared__ __align__(16) char sm[];
    float* A_s  = (float*)(sm + SM_A);
    float* W1_s = (float*)(sm + SM_W1);
    float* W2_s = (float*)(sm + SM_W2);
    float* b0_s = (float*)(sm + SM_B0);
    float* b1_s = (float*)(sm + SM_B1);
    int*   bat_s = (int*)(sm + SM_BAT);

    int tid = threadIdx.x;
    int wid = tid >> 5;
    int lane = tid & 31;
    int g = lane >> 2;
    int t = lane & 3;
    int mw = wid & 3;                 // row group (32 rows)
    int ncol0 = (wid >> 2) * 32;      // column base (32 cols)
    int prow = tid >> 3;              // gather: node slot (0..31)
    int c0 = tid & 7;                 // gather: first float4 slice
    int c1 = c0 + 8;                  // gather: second float4 slice

    // stage weights once per block (BN folded into W1), tf32-rounded
    for (int i = tid; i < FEAT * FEAT; i += 256) {
        int n = i & 63;
        float s = __ldg(gam + n) * rsqrtf(__ldg(var + n) + BN_EPS);
        W1_s[(i >> 6) * W_STRIDE + n] = __uint_as_float(f2tf32(__ldg(wa + i) * s));
        W2_s[(i >> 6) * W_STRIDE + n] = __uint_as_float(f2tf32(__ldg(wb + i)));
    }
    if (tid < FEAT) {
        float s = __ldg(gam + tid) * rsqrtf(__ldg(var + tid) + BN_EPS);
        b0_s[tid] = (__ldg(ba + tid) - __ldg(mu + tid)) * s + __ldg(bet + tid);
        b1_s[tid] = __ldg(bb + tid);
    }
    // visibility of W covered by the gather->GEMM sync inside the loop

    for (int tile = blockIdx.x; tile < NTILES; tile += GRID_CONV) {
        int node_base = tile * 128;

        // ============ gather phase: 32 nodes/pass, 4 passes ============
#pragma unroll
        for (int s = 0; s < 4; s++) {
            int row = s * 32 + prow;
            int node = node_base + row;
            float4 A = make_float4(0.f, 0.f, 0.f, 0.f);
            float4 B = make_float4(0.f, 0.f, 0.f, 0.f);
            if (node < N_NODES) {
                const float4* hn = (const float4*)(h + (size_t)node * FEAT);
                A = __ldg(hn + c0);
                B = __ldg(hn + c1);
                int dg = __ldg(deg + node);
                if (dg > CAP) dg = CAP;
                const int* lst = csr + (size_t)node * CAP;
                int r = dg - 1;
                for (int i = 0; i < dg; i += 4) {
                    int j1 = i + 1 > r ? r : i + 1;
                    int j2 = i + 2 > r ? r : i + 2;
                    int j3 = i + 3 > r ? r : i + 3;
                    float m1 = (i + 1 <= r) ? 1.f : 0.f;
                    float m2 = (i + 2 <= r) ? 1.f : 0.f;
                    float m3 = (i + 3 <= r) ? 1.f : 0.f;
                    int s0 = __ldg(lst + i);
                    int s1 = __ldg(lst + j1);
                    int s2 = __ldg(lst + j2);
                    int s3 = __ldg(lst + j3);
                    const float4* h0 = (const float4*)(h + (size_t)s0 * FEAT);
                    const float4* h1 = (const float4*)(h + (size_t)s1 * FEAT);
                    const float4* h2 = (const float4*)(h + (size_t)s2 * FEAT);
                    const float4* h3 = (const float4*)(h + (size_t)s3 * FEAT);
                    float4 v00 = __ldg(h0 + c0), v01 = __ldg(h0 + c1);
                    float4 v10 = __ldg(h1 + c0), v11 = __ldg(h1 + c1);
                    float4 v20 = __ldg(h2 + c0), v21 = __ldg(h2 + c1);
                    float4 v30 = __ldg(h3 + c0), v31 = __ldg(h3 + c1);
                    add4(A, v00);      add4(B, v01);
                    fma4(A, m1, v10);  fma4(B, m1, v11);
                    fma4(A, m2, v20);  fma4(B, m2, v21);
                    fma4(A, m3, v30);  fma4(B, m3, v31);
                }
            }
            *reinterpret_cast<float4*>(A_s + row * A_STRIDE + c0 * 4) = A;
            *reinterpret_cast<float4*>(A_s + row * A_STRIDE + c1 * 4) = B;
            if (c0 == 0)
                bat_s[row] = (node < N_NODES) ? __ldg(batch + node) : -1;
        }
        __syncthreads();   // tile gathered (also orders weight staging)

        // ============ GEMM phase ============
        const float* Aw = A_s + (mw * 32) * A_STRIDE;
        float* Aww = A_s + (mw * 32) * A_STRIDE;

        float acc[2][4][4];

#define GEMM_LAYER(WS)                                                        \
    {                                                                         \
        _Pragma("unroll")                                                     \
        for (int mt = 0; mt < 2; mt++)                                        \
            _Pragma("unroll")                                                 \
            for (int nt = 0; nt < 4; nt++)                                    \
                _Pragma("unroll")                                             \
                for (int e = 0; e < 4; e++) acc[mt][nt][e] = 0.0f;            \
        _Pragma("unroll")                                                     \
        for (int ks = 0; ks < 8; ks++) {                                      \
            uint32_t af[2][4];                                                \
            _Pragma("unroll")                                                 \
            for (int mt = 0; mt < 2; mt++) {                                  \
                const float* ap = Aw + (mt * 16 + g) * A_STRIDE + ks * 8 + t; \
                af[mt][0] = f2tf32(ap[0]);                                    \
                af[mt][1] = f2tf32(ap[8 * A_STRIDE]);                         \
                af[mt][2] = f2tf32(ap[4]);                                    \
                af[mt][3] = f2tf32(ap[8 * A_STRIDE + 4]);                     \
            }                                                                 \
            _Pragma("unroll")                                                 \
            for (int nt = 0; nt < 4; nt++) {                                  \
                int col = ncol0 + nt * 8 + g;                                 \
                uint32_t b0 = __float_as_uint(WS[(ks * 8 + t) * W_STRIDE + col]);     \
                uint32_t b1 = __float_as_uint(WS[(ks * 8 + t + 4) * W_STRIDE + col]); \
                mma_tf32(acc[0][nt], af[0], b0, b1);                          \
                mma_tf32(acc[1][nt], af[1], b0, b1);                          \
            }                                                                 \
        }                                                                     \
    }

        // ---- Layer 1 ----
        GEMM_LAYER(W1_s);
        __syncthreads();   // all warps done reading A1

        // bias + relu, write u in place
#pragma unroll
        for (int mt = 0; mt < 2; mt++) {
#pragma unroll
            for (int nt = 0; nt < 4; nt++) {
                int col = ncol0 + nt * 8 + 2 * t;
                float bc0 = b0_s[col], bc1 = b0_s[col + 1];
                float* r0 = Aww + (mt * 16 + g) * A_STRIDE + col;
                float* r1 = Aww + (mt * 16 + g + 8) * A_STRIDE + col;
                r0[0] = fmaxf(acc[mt][nt][0] + bc0, 0.0f);
                r0[1] = fmaxf(acc[mt][nt][1] + bc1, 0.0f);
                r1[0] = fmaxf(acc[mt][nt][2] + bc0, 0.0f);
                r1[1] = fmaxf(acc[mt][nt][3] + bc1, 0.0f);
            }
        }
        __syncthreads();   // u complete

        // ---- Layer 2 ----
        GEMM_LAYER(W2_s);

        // ---- epilogue ----
        if (mode == 0) {
#pragma unroll
            for (int mt = 0; mt < 2; mt++) {
                int node0 = node_base + mw * 32 + mt * 16 + g;
                int node1 = node0 + 8;
#pragma unroll
                for (int nt = 0; nt < 4; nt++) {
                    int col = ncol0 + nt * 8 + 2 * t;
                    float bc0 = b1_s[col], bc1 = b1_s[col + 1];
                    if (node0 < N_NODES) {
                        float2 v = make_float2(fmaxf(acc[mt][nt][0] + bc0, 0.0f),
                                               fmaxf(acc[mt][nt][1] + bc1, 0.0f));
                        *(float2*)(out + (size_t)node0 * FEAT + col) = v;
                    }
                    if (node1 < N_NODES) {
                        float2 v = make_float2(fmaxf(acc[mt][nt][2] + bc0, 0.0f),
                                               fmaxf(acc[mt][nt][3] + bc1, 0.0f));
                        *(float2*)(out + (size_t)node1 * FEAT + col) = v;
                    }
                }
            }
        } else {
            __syncthreads();   // all warps done reading A (layer 2)
#pragma unroll
            for (int mt = 0; mt < 2; mt++) {
#pragma unroll
                for (int nt = 0; nt < 4; nt++) {
                    int col = ncol0 + nt * 8 + 2 * t;
                    float bc0 = b1_s[col], bc1 = b1_s[col + 1];
                    float* r0 = Aww + (mt * 16 + g) * A_STRIDE + col;
                    float* r1 = Aww + (mt * 16 + g + 8) * A_STRIDE + col;
                    r0[0] = acc[mt][nt][0] + bc0;
                    r0[1] = acc[mt][nt][1] + bc1;
                    r1[0] = acc[mt][nt][2] + bc0;
                    r1[1] = acc[mt][nt][3] + bc1;
                }
            }
            __syncthreads();

            // segmented column reduction over sorted batch ids
            int col = tid & 63;
            int quarter = tid >> 6;       // 0..3, 32 rows each
            int cur = -1;
            float run = 0.0f;
#pragma unroll 8
            for (int r = 0; r < 32; r++) {
                int rr = quarter * 32 + r;
                int b = bat_s[rr];
                float v = A_s[rr * A_STRIDE + col];
                if (b != cur) {
                    if (cur >= 0) {
                        float* q = sums + (size_t)cur * FEAT + col;
                        asm volatile("red.global.add.f32 [%0], %1;"
                                     :: "l"(q), "f"(run) : "memory");
                    }
                    cur = b;
                    run = 0.0f;
                }
                run += v;
            }
            if (cur >= 0) {
                float* q = sums + (size_t)cur * FEAT + col;
                asm volatile("red.global.add.f32 [%0], %1;"
                             :: "l"(q), "f"(run) : "memory");
            }
        }
        __syncthreads();   // done with A before next tile's gather
#undef GEMM_LAYER
    }
}

// ---------------------------------------------------------------------------
__global__ __launch_bounds__(64) void classify_kernel(
    const float* __restrict__ sums,
    const float* __restrict__ cnts,
    const float* __restrict__ wc,
    const float* __restrict__ bc,
    float* __restrict__ out)
{
    int g = blockIdx.x;
    int tid = threadIdx.x;
    __shared__ float p[FEAT];
    float cnt = fmaxf(__ldg(cnts + g), 1.0f);
    p[tid] = sums[(size_t)g * FEAT + tid] / cnt;
    __syncthreads();
    if (tid < N_CLS) {
        float acc = bc[tid];
#pragma unroll
        for (int k = 0; k < FEAT; k++) {
            acc = fmaf(p[k], wc[k * N_CLS + tid], acc);
        }
        out[(size_t)g * N_CLS + tid] = acc;
    }
}

// ---------------------------------------------------------------------------
extern "C" void kernel_launch(void* const* d_in, const int* in_sizes, int n_in,
                              void* d_out, int out_size)
{
    const float* x   = (const float*)d_in[0];
    const int*   ei  = (const int*)d_in[1];
    const int*   bat = (const int*)d_in[2];
    const float* w0a = (const float*)d_in[3];
    const float* b0a = (const float*)d_in[4];
    const float* g0  = (const float*)d_in[5];
    const float* be0 = (const float*)d_in[6];
    const float* m0  = (const float*)d_in[7];
    const float* v0  = (const float*)d_in[8];
    const float* w0b = (const float*)d_in[9];
    const float* b0b = (const float*)d_in[10];
    const float* w1a = (const float*)d_in[11];
    const float* b1a = (const float*)d_in[12];
    const float* g1  = (const float*)d_in[13];
    const float* be1 = (const float*)d_in[14];
    const float* m1  = (const float*)d_in[15];
    const float* v1  = (const float*)d_in[16];
    const float* w1b = (const float*)d_in[17];
    const float* b1b = (const float*)d_in[18];
    const float* wc  = (const float*)d_in[19];
    const float* bc  = (const float*)d_in[20];
    float* out = (float*)d_out;

    const int* src = ei;            // edge_index[0]
    const int* dst = ei + N_EDGES;  // edge_index[1]

    float *p_h1, *p_sums, *p_cnts;
    int *p_deg, *p_csr;
    cudaGetSymbolAddress((void**)&p_h1,   g_h1);
    cudaGetSymbolAddress((void**)&p_sums, g_sums);
    cudaGetSymbolAddress((void**)&p_cnts, g_cnts);
    cudaGetSymbolAddress((void**)&p_deg,  g_deg);
    cudaGetSymbolAddress((void**)&p_csr,  g_csr);

    static bool attr_done = false;
    if (!attr_done) {
        cudaFuncSetAttribute(conv_kernel,
                             cudaFuncAttributeMaxDynamicSharedMemorySize,
                             SM_TOTAL);
        attr_done = true;
    }

    const int fill_blocks = (N_EDGES + 255) / 256;
    const int node_blocks = (N_NODES + 255) / 256;

    // ---- CSR build + pool init ----
    cudaMemsetAsync(p_deg, 0, (size_t)N_NODES * sizeof(int));
    cudaMemsetAsync(p_sums, 0, (size_t)N_GRAPHS * FEAT * sizeof(float));
    cudaMemsetAsync(p_cnts, 0, (size_t)N_GRAPHS * sizeof(float));
    fill_kernel<<<fill_blocks, 256>>>(src, dst, p_deg, p_csr);
    count_kernel<<<node_blocks, 256>>>(bat, p_cnts);

    // ---- Conv 0 (fused gather + MLP) ----
    conv_kernel<<<GRID_CONV, 256, SM_TOTAL>>>(
        x, p_deg, p_csr, w0a, b0a, g0, be0, m0, v0,
        w0b, b0b, p_h1, bat, p_sums, /*mode=*/0);

    // ---- Conv 1 (fused gather + MLP + pooled sum) ----
    conv_kernel<<<GRID_CONV, 256, SM_TOTAL>>>(
        p_h1, p_deg, p_csr, w1a, b1a, g1, be1, m1, v1,
        w1b, b1b, /*out unused*/ p_h1, bat, p_sums, /*mode=*/1);

    // ---- Classify ----
    classify_kernel<<<N_GRAPHS, 64>>>(p_sums, p_cnts, wc, bc, out);
}

// round 14
// speedup vs baseline: 1.8690x; 1.0335x over previous
#include <cuda_runtime.h>
#include <cuda_bf16.h>
#include <math.h>
#include <stdint.h>

#define N_NODES 100000
#define N_EDGES 1000000
#define FEAT 64
#define N_GRAPHS 512
#define N_CLS 10
#define BN_EPS 1e-5f
#define CAP 96
#define UNR 16

#define NTILES 782
#define GRID_CONV 444

// Scratch (device globals — no allocation allowed)
__device__ float g_h1[N_NODES * FEAT];
__device__ float g_sums[N_GRAPHS * FEAT];
__device__ float g_cnts[N_GRAPHS];
__device__ int   g_deg[N_NODES];
__device__ int   g_csr[N_NODES * CAP];

// ---------------------------------------------------------------------------
// helpers
// ---------------------------------------------------------------------------
__device__ __forceinline__ uint32_t f2tf32(float x) {
    uint32_t r;
    asm("cvt.rna.tf32.f32 %0, %1;" : "=r"(r) : "f"(x));
    return r;
}

__device__ __forceinline__ void mma_tf32(float* c, const uint32_t* a,
                                         uint32_t b0, uint32_t b1) {
    asm("mma.sync.aligned.m16n8k8.row.col.f32.tf32.tf32.f32 "
        "{%0,%1,%2,%3}, {%4,%5,%6,%7}, {%8,%9}, {%0,%1,%2,%3};"
        : "+f"(c[0]), "+f"(c[1]), "+f"(c[2]), "+f"(c[3])
        : "r"(a[0]), "r"(a[1]), "r"(a[2]), "r"(a[3]), "r"(b0), "r"(b1));
}

__device__ __forceinline__ void add4(float4& a, const float4& v) {
    a.x += v.x; a.y += v.y; a.z += v.z; a.w += v.w;
}

// SMEM layout (bytes)
#define A_STRIDE 68
#define W_STRIDE 72
#define SM_A     0
#define SM_W1    34816
#define SM_W2    (SM_W1 + 18432)
#define SM_B0    (SM_W2 + 18432)
#define SM_B1    (SM_B0 + 256)
#define SM_BAT   (SM_B1 + 256)
#define SM_TOTAL (SM_BAT + 512)          // 72704 bytes -> 3 blocks/SM

// ---------------------------------------------------------------------------
// CSR fill: csr[dst*CAP + pos] = src
// ---------------------------------------------------------------------------
__global__ __launch_bounds__(256) void fill_kernel(
    const int* __restrict__ src, const int* __restrict__ dst,
    int* __restrict__ deg, int* __restrict__ csr)
{
    int e = blockIdx.x * blockDim.x + threadIdx.x;
    if (e >= N_EDGES) return;
    int d = __ldg(dst + e);
    int pos = atomicAdd(deg + d, 1);
    if (pos < CAP) csr[d * CAP + pos] = __ldg(src + e);
}

// ---------------------------------------------------------------------------
__global__ __launch_bounds__(256) void count_kernel(
    const int* __restrict__ batch, float* __restrict__ cnts)
{
    int i = blockIdx.x * blockDim.x + threadIdx.x;
    if (i < N_NODES) atomicAdd(cnts + __ldg(batch + i), 1.0f);
}

// ---------------------------------------------------------------------------
// Fused gather + GIN MLP, persistent, all-warp phases.
// Gather: 8 threads/node (two float4 slices each), 32 nodes/pass, 4 passes.
//   Indices loaded as 4x int4 (one level), then UNR=16 statically-unrolled
//   predicated h-loads (second level) -> 2 dependency levels per pass.
//   Dynamic remainder loop only for deg > 16 (~11% of nodes).
// GEMM: 8-warp split tf32 (4 row x 2 col groups).
// mode 0: out[node] = relu(mlp(t))
// mode 1: segmented block-reduce mlp(t) rows by sorted batch -> red to sums
// ---------------------------------------------------------------------------
__global__ __launch_bounds__(256, 3) void conv_kernel(
    const float* __restrict__ h,
    const int* __restrict__ deg, const int* __restrict__ csr,
    const float* __restrict__ wa, const float* __restrict__ ba,
    const float* __restrict__ gam, const float* __restrict__ bet,
    const float* __restrict__ mu,  const float* __restrict__ var,
    const float* __restrict__ wb,  const float* __restrict__ bb,
    float* __restrict__ out, const int* __restrict__ batch,
    float* __restrict__ sums, int mode)
{
    extern __shared__ __align__(16) char sm[];
    float* A_s  = (float*)(sm + SM_A);
    float* W1_s = (float*)(sm + SM_W1);
    float* W2_s = (float*)(sm + SM_W2);
    float* b0_s = (float*)(sm + SM_B0);
    float* b1_s = (float*)(sm + SM_B1);
    int*   bat_s = (int*)(sm + SM_BAT);

    int tid = threadIdx.x;
    int wid = tid >> 5;
    int lane = tid & 31;
    int g = lane >> 2;
    int t = lane & 3;
    int mw = wid & 3;                 // row group (32 rows)
    int ncol0 = (wid >> 2) * 32;      // column base (32 cols)
    int prow = tid >> 3;              // gather: node slot (0..31)
    int c0 = tid & 7;                 // gather: first float4 slice
    int c1 = c0 + 8;                  // gather: second float4 slice

    // stage weights once per block (BN folded into W1), tf32-rounded
    for (int i = tid; i < FEAT * FEAT; i += 256) {
        int n = i & 63;
        float s = __ldg(gam + n) * rsqrtf(__ldg(var + n) + BN_EPS);
        W1_s[(i >> 6) * W_STRIDE + n] = __uint_as_float(f2tf32(__ldg(wa + i) * s));
        W2_s[(i >> 6) * W_STRIDE + n] = __uint_as_float(f2tf32(__ldg(wb + i)));
    }
    if (tid < FEAT) {
        float s = __ldg(gam + tid) * rsqrtf(__ldg(var + tid) + BN_EPS);
        b0_s[tid] = (__ldg(ba + tid) - __ldg(mu + tid)) * s + __ldg(bet + tid);
        b1_s[tid] = __ldg(bb + tid);
    }
    // visibility of W covered by the gather->GEMM sync inside the loop

    for (int tile = blockIdx.x; tile < NTILES; tile += GRID_CONV) {
        int node_base = tile * 128;

        // ============ gather phase: 32 nodes/pass, 4 passes ============
#pragma unroll
        for (int s = 0; s < 4; s++) {
            int row = s * 32 + prow;
            int node = node_base + row;
            float4 A = make_float4(0.f, 0.f, 0.f, 0.f);
            float4 B = make_float4(0.f, 0.f, 0.f, 0.f);
            if (node < N_NODES) {
                const float4* hn = (const float4*)(h + (size_t)node * FEAT);
                A = __ldg(hn + c0);
                B = __ldg(hn + c1);
                int dg = __ldg(deg + node);
                if (dg > CAP) dg = CAP;
                const int* lst = csr + (size_t)node * CAP;

                // level 1: first 16 indices in four int4 loads
                const int4* lst4 = (const int4*)lst;
                int4 I0 = __ldg(lst4 + 0);
                int4 I1 = __ldg(lst4 + 1);
                int4 I2 = __ldg(lst4 + 2);
                int4 I3 = __ldg(lst4 + 3);
                int idx[UNR] = {I0.x, I0.y, I0.z, I0.w,
                                I1.x, I1.y, I1.z, I1.w,
                                I2.x, I2.y, I2.z, I2.w,
                                I3.x, I3.y, I3.z, I3.w};

                // level 2: statically unrolled predicated gathers
#pragma unroll
                for (int k = 0; k < UNR; k++) {
                    float4 vA = make_float4(0.f, 0.f, 0.f, 0.f);
                    float4 vB = make_float4(0.f, 0.f, 0.f, 0.f);
                    if (k < dg) {
                        const float4* hp =
                            (const float4*)(h + (size_t)idx[k] * FEAT);
                        vA = __ldg(hp + c0);
                        vB = __ldg(hp + c1);
                    }
                    add4(A, vA);
                    add4(B, vB);
                }
                // rare tail: deg > 16
                for (int k = UNR; k < dg; k++) {
                    int s0 = __ldg(lst + k);
                    const float4* hp = (const float4*)(h + (size_t)s0 * FEAT);
                    add4(A, __ldg(hp + c0));
                    add4(B, __ldg(hp + c1));
                }
            }
            *reinterpret_cast<float4*>(A_s + row * A_STRIDE + c0 * 4) = A;
            *reinterpret_cast<float4*>(A_s + row * A_STRIDE + c1 * 4) = B;
            if (c0 == 0)
                bat_s[row] = (node < N_NODES) ? __ldg(batch + node) : -1;
        }
        __syncthreads();   // tile gathered (also orders weight staging)

        // ============ GEMM phase ============
        const float* Aw = A_s + (mw * 32) * A_STRIDE;
        float* Aww = A_s + (mw * 32) * A_STRIDE;

        float acc[2][4][4];

#define GEMM_LAYER(WS)                                                        \
    {                                                                         \
        _Pragma("unroll")                                                     \
        for (int mt = 0; mt < 2; mt++)                                        \
            _Pragma("unroll")                                                 \
            for (int nt = 0; nt < 4; nt++)                                    \
                _Pragma("unroll")                                             \
                for (int e = 0; e < 4; e++) acc[mt][nt][e] = 0.0f;            \
        _Pragma("unroll")                                                     \
        for (int ks = 0; ks < 8; ks++) {                                      \
            uint32_t af[2][4];                                                \
            _Pragma("unroll")                                                 \
            for (int mt = 0; mt < 2; mt++) {                                  \
                const float* ap = Aw + (mt * 16 + g) * A_STRIDE + ks * 8 + t; \
                af[mt][0] = f2tf32(ap[0]);                                    \
                af[mt][1] = f2tf32(ap[8 * A_STRIDE]);                         \
                af[mt][2] = f2tf32(ap[4]);                                    \
                af[mt][3] = f2tf32(ap[8 * A_STRIDE + 4]);                     \
            }                                                                 \
            _Pragma("unroll")                                                 \
            for (int nt = 0; nt < 4; nt++) {                                  \
                int col = ncol0 + nt * 8 + g;                                 \
                uint32_t b0 = __float_as_uint(WS[(ks * 8 + t) * W_STRIDE + col]);     \
                uint32_t b1 = __float_as_uint(WS[(ks * 8 + t + 4) * W_STRIDE + col]); \
                mma_tf32(acc[0][nt], af[0], b0, b1);                          \
                mma_tf32(acc[1][nt], af[1], b0, b1);                          \
            }                                                                 \
        }                                                                     \
    }

        // ---- Layer 1 ----
        GEMM_LAYER(W1_s);
        __syncthreads();   // all warps done reading A1

        // bias + relu, write u in place
#pragma unroll
        for (int mt = 0; mt < 2; mt++) {
#pragma unroll
            for (int nt = 0; nt < 4; nt++) {
                int col = ncol0 + nt * 8 + 2 * t;
                float bc0 = b0_s[col], bc1 = b0_s[col + 1];
                float* r0 = Aww + (mt * 16 + g) * A_STRIDE + col;
                float* r1 = Aww + (mt * 16 + g + 8) * A_STRIDE + col;
                r0[0] = fmaxf(acc[mt][nt][0] + bc0, 0.0f);
                r0[1] = fmaxf(acc[mt][nt][1] + bc1, 0.0f);
                r1[0] = fmaxf(acc[mt][nt][2] + bc0, 0.0f);
                r1[1] = fmaxf(acc[mt][nt][3] + bc1, 0.0f);
            }
        }
        __syncthreads();   // u complete

        // ---- Layer 2 ----
        GEMM_LAYER(W2_s);

        // ---- epilogue ----
        if (mode == 0) {
#pragma unroll
            for (int mt = 0; mt < 2; mt++) {
                int node0 = node_base + mw * 32 + mt * 16 + g;
                int node1 = node0 + 8;
#pragma unroll
                for (int nt = 0; nt < 4; nt++) {
                    int col = ncol0 + nt * 8 + 2 * t;
                    float bc0 = b1_s[col], bc1 = b1_s[col + 1];
                    if (node0 < N_NODES) {
                        float2 v = make_float2(fmaxf(acc[mt][nt][0] + bc0, 0.0f),
                                               fmaxf(acc[mt][nt][1] + bc1, 0.0f));
                        *(float2*)(out + (size_t)node0 * FEAT + col) = v;
                    }
                    if (node1 < N_NODES) {
                        float2 v = make_float2(fmaxf(acc[mt][nt][2] + bc0, 0.0f),
                                               fmaxf(acc[mt][nt][3] + bc1, 0.0f));
                        *(float2*)(out + (size_t)node1 * FEAT + col) = v;
                    }
                }
            }
        } else {
            __syncthreads();   // all warps done reading A (layer 2)
#pragma unroll
            for (int mt = 0; mt < 2; mt++) {
#pragma unroll
                for (int nt = 0; nt < 4; nt++) {
                    int col = ncol0 + nt * 8 + 2 * t;
                    float bc0 = b1_s[col], bc1 = b1_s[col + 1];
                    float* r0 = Aww + (mt * 16 + g) * A_STRIDE + col;
                    float* r1 = Aww + (mt * 16 + g + 8) * A_STRIDE + col;
                    r0[0] = acc[mt][nt][0] + bc0;
                    r0[1] = acc[mt][nt][1] + bc1;
                    r1[0] = acc[mt][nt][2] + bc0;
                    r1[1] = acc[mt][nt][3] + bc1;
                }
            }
            __syncthreads();

            // segmented column reduction over sorted batch ids
            int col = tid & 63;
            int quarter = tid >> 6;       // 0..3, 32 rows each
            int cur = -1;
            float run = 0.0f;
#pragma unroll 8
            for (int r = 0; r < 32; r++) {
                int rr = quarter * 32 + r;
                int b = bat_s[rr];
                float v = A_s[rr * A_STRIDE + col];
                if (b != cur) {
                    if (cur >= 0) {
                        float* q = sums + (size_t)cur * FEAT + col;
                        asm volatile("red.global.add.f32 [%0], %1;"
                                     :: "l"(q), "f"(run) : "memory");
                    }
                    cur = b;
                    run = 0.0f;
                }
                run += v;
            }
            if (cur >= 0) {
                float* q = sums + (size_t)cur * FEAT + col;
                asm volatile("red.global.add.f32 [%0], %1;"
                             :: "l"(q), "f"(run) : "memory");
            }
        }
        __syncthreads();   // done with A before next tile's gather
#undef GEMM_LAYER
    }
}

// ---------------------------------------------------------------------------
__global__ __launch_bounds__(64) void classify_kernel(
    const float* __restrict__ sums,
    const float* __restrict__ cnts,
    const float* __restrict__ wc,
    const float* __restrict__ bc,
    float* __restrict__ out)
{
    int g = blockIdx.x;
    int tid = threadIdx.x;
    __shared__ float p[FEAT];
    float cnt = fmaxf(__ldg(cnts + g), 1.0f);
    p[tid] = sums[(size_t)g * FEAT + tid] / cnt;
    __syncthreads();
    if (tid < N_CLS) {
        float acc = bc[tid];
#pragma unroll
        for (int k = 0; k < FEAT; k++) {
            acc = fmaf(p[k], wc[k * N_CLS + tid], acc);
        }
        out[(size_t)g * N_CLS + tid] = acc;
    }
}

// ---------------------------------------------------------------------------
extern "C" void kernel_launch(void* const* d_in, const int* in_sizes, int n_in,
                              void* d_out, int out_size)
{
    const float* x   = (const float*)d_in[0];
    const int*   ei  = (const int*)d_in[1];
    const int*   bat = (const int*)d_in[2];
    const float* w0a = (const float*)d_in[3];
    const float* b0a = (const float*)d_in[4];
    const float* g0  = (const float*)d_in[5];
    const float* be0 = (const float*)d_in[6];
    const float* m0  = (const float*)d_in[7];
    const float* v0  = (const float*)d_in[8];
    const float* w0b = (const float*)d_in[9];
    const float* b0b = (const float*)d_in[10];
    const float* w1a = (const float*)d_in[11];
    const float* b1a = (const float*)d_in[12];
    const float* g1  = (const float*)d_in[13];
    const float* be1 = (const float*)d_in[14];
    const float* m1  = (const float*)d_in[15];
    const float* v1  = (const float*)d_in[16];
    const float* w1b = (const float*)d_in[17];
    const float* b1b = (const float*)d_in[18];
    const float* wc  = (const float*)d_in[19];
    const float* bc  = (const float*)d_in[20];
    float* out = (float*)d_out;

    const int* src = ei;            // edge_index[0]
    const int* dst = ei + N_EDGES;  // edge_index[1]

    float *p_h1, *p_sums, *p_cnts;
    int *p_deg, *p_csr;
    cudaGetSymbolAddress((void**)&p_h1,   g_h1);
    cudaGetSymbolAddress((void**)&p_sums, g_sums);
    cudaGetSymbolAddress((void**)&p_cnts, g_cnts);
    cudaGetSymbolAddress((void**)&p_deg,  g_deg);
    cudaGetSymbolAddress((void**)&p_csr,  g_csr);

    static bool attr_done = false;
    if (!attr_done) {
        cudaFuncSetAttribute(conv_kernel,
                             cudaFuncAttributeMaxDynamicSharedMemorySize,
                             SM_TOTAL);
        attr_done = true;
    }

    const int fill_blocks = (N_EDGES + 255) / 256;
    const int node_blocks = (N_NODES + 255) / 256;

    // ---- CSR build + pool init ----
    cudaMemsetAsync(p_deg, 0, (size_t)N_NODES * sizeof(int));
    cudaMemsetAsync(p_sums, 0, (size_t)N_GRAPHS * FEAT * sizeof(float));
    cudaMemsetAsync(p_cnts, 0, (size_t)N_GRAPHS * sizeof(float));
    fill_kernel<<<fill_blocks, 256>>>(src, dst, p_deg, p_csr);
    count_kernel<<<node_blocks, 256>>>(bat, p_cnts);

    // ---- Conv 0 (fused gather + MLP) ----
    conv_kernel<<<GRID_CONV, 256, SM_TOTAL>>>(
        x, p_deg, p_csr, w0a, b0a, g0, be0, m0, v0,
        w0b, b0b, p_h1, bat, p_sums, /*mode=*/0);

    // ---- Conv 1 (fused gather + MLP + pooled sum) ----
    conv_kernel<<<GRID_CONV, 256, SM_TOTAL>>>(
        p_h1, p_deg, p_csr, w1a, b1a, g1, be1, m1, v1,
        w1b, b1b, /*out unused*/ p_h1, bat, p_sums, /*mode=*/1);

    // ---- Classify ----
    classify_kernel<<<N_GRAPHS, 64>>>(p_sums, p_cnts, wc, bc, out);
}

// round 15
// speedup vs baseline: 2.0179x; 1.0797x over previous
#include <cuda_runtime.h>
#include <cuda_bf16.h>
#include <math.h>
#include <stdint.h>

#define N_NODES 100000
#define N_EDGES 1000000
#define FEAT 64
#define N_GRAPHS 512
#define N_CLS 10
#define BN_EPS 1e-5f
#define CAP 96
#define UNR 16

#define NTILES 782
#define GRID_CONV 444

// Scratch (device globals — no allocation allowed)
__device__ __nv_bfloat16 g_xb[N_NODES * FEAT];   // x in bf16
__device__ __nv_bfloat16 g_h1[N_NODES * FEAT];   // h1 in bf16
__device__ float g_sums[N_GRAPHS * FEAT];
__device__ float g_cnts[N_GRAPHS];
__device__ int   g_deg[N_NODES];
__device__ int   g_csr[N_NODES * CAP];

// ---------------------------------------------------------------------------
// helpers
// ---------------------------------------------------------------------------
__device__ __forceinline__ uint32_t f2tf32(float x) {
    uint32_t r;
    asm("cvt.rna.tf32.f32 %0, %1;" : "=r"(r) : "f"(x));
    return r;
}

__device__ __forceinline__ uint32_t pack_bf16x2(float lo, float hi) {
    uint32_t r;
    asm("cvt.rn.bf16x2.f32 %0, %1, %2;" : "=r"(r) : "f"(hi), "f"(lo));
    return r;
}

__device__ __forceinline__ void mma_tf32(float* c, const uint32_t* a,
                                         uint32_t b0, uint32_t b1) {
    asm("mma.sync.aligned.m16n8k8.row.col.f32.tf32.tf32.f32 "
        "{%0,%1,%2,%3}, {%4,%5,%6,%7}, {%8,%9}, {%0,%1,%2,%3};"
        : "+f"(c[0]), "+f"(c[1]), "+f"(c[2]), "+f"(c[3])
        : "r"(a[0]), "r"(a[1]), "r"(a[2]), "r"(a[3]), "r"(b0), "r"(b1));
}

// accumulate 8 bf16 (one uint4) into 8 fp32 (exact unpack: <<16)
__device__ __forceinline__ void bacc(float* a, uint4 v) {
    a[0] += __uint_as_float(v.x << 16);
    a[1] += __uint_as_float(v.x & 0xFFFF0000u);
    a[2] += __uint_as_float(v.y << 16);
    a[3] += __uint_as_float(v.y & 0xFFFF0000u);
    a[4] += __uint_as_float(v.z << 16);
    a[5] += __uint_as_float(v.z & 0xFFFF0000u);
    a[6] += __uint_as_float(v.w << 16);
    a[7] += __uint_as_float(v.w & 0xFFFF0000u);
}

// SMEM layout (bytes)
#define A_STRIDE 68
#define W_STRIDE 72
#define SM_A     0
#define SM_W1    34816
#define SM_W2    (SM_W1 + 18432)
#define SM_B0    (SM_W2 + 18432)
#define SM_B1    (SM_B0 + 256)
#define SM_BAT   (SM_B1 + 256)
#define SM_TOTAL (SM_BAT + 512)          // 72704 bytes -> 3 blocks/SM

// ---------------------------------------------------------------------------
// x -> bf16 conversion (one thread = 8 elements)
// ---------------------------------------------------------------------------
__global__ __launch_bounds__(256) void cvt_kernel(
    const float* __restrict__ x, __nv_bfloat16* __restrict__ xb)
{
    int i = blockIdx.x * 256 + threadIdx.x;
    if (i >= N_NODES * FEAT / 8) return;
    const float4* xp = (const float4*)x + 2 * i;
    float4 a = __ldg(xp);
    float4 b = __ldg(xp + 1);
    uint4 r;
    r.x = pack_bf16x2(a.x, a.y);
    r.y = pack_bf16x2(a.z, a.w);
    r.z = pack_bf16x2(b.x, b.y);
    r.w = pack_bf16x2(b.z, b.w);
    ((uint4*)xb)[i] = r;
}

// ---------------------------------------------------------------------------
// CSR fill: csr[dst*CAP + pos] = src
// ---------------------------------------------------------------------------
__global__ __launch_bounds__(256) void fill_kernel(
    const int* __restrict__ src, const int* __restrict__ dst,
    int* __restrict__ deg, int* __restrict__ csr)
{
    int e = blockIdx.x * blockDim.x + threadIdx.x;
    if (e >= N_EDGES) return;
    int d = __ldg(dst + e);
    int pos = atomicAdd(deg + d, 1);
    if (pos < CAP) csr[d * CAP + pos] = __ldg(src + e);
}

// ---------------------------------------------------------------------------
__global__ __launch_bounds__(256) void count_kernel(
    const int* __restrict__ batch, float* __restrict__ cnts)
{
    int i = blockIdx.x * blockDim.x + threadIdx.x;
    if (i < N_NODES) atomicAdd(cnts + __ldg(batch + i), 1.0f);
}

// ---------------------------------------------------------------------------
// Fused gather + GIN MLP, persistent, all-warp phases. h stored in bf16:
// one neighbor row = 128B = one L2 line; 8 threads/node, one uint4 each.
// Accumulation in fp32; A_s fp32; GEMM tf32 unchanged.
// mode 0: out[node] = bf16(relu(mlp(t)))
// mode 1: segmented block-reduce mlp(t) rows by sorted batch -> red to sums
// ---------------------------------------------------------------------------
__global__ __launch_bounds__(256, 3) void conv_kernel(
    const __nv_bfloat16* __restrict__ h,
    const int* __restrict__ deg, const int* __restrict__ csr,
    const float* __restrict__ wa, const float* __restrict__ ba,
    const float* __restrict__ gam, const float* __restrict__ bet,
    const float* __restrict__ mu,  const float* __restrict__ var,
    const float* __restrict__ wb,  const float* __restrict__ bb,
    __nv_bfloat16* __restrict__ out, const int* __restrict__ batch,
    float* __restrict__ sums, int mode)
{
    extern __shared__ __align__(16) char sm[];
    float* A_s  = (float*)(sm + SM_A);
    float* W1_s = (float*)(sm + SM_W1);
    float* W2_s = (float*)(sm + SM_W2);
    float* b0_s = (float*)(sm + SM_B0);
    float* b1_s = (float*)(sm + SM_B1);
    int*   bat_s = (int*)(sm + SM_BAT);

    int tid = threadIdx.x;
    int wid = tid >> 5;
    int lane = tid & 31;
    int g = lane >> 2;
    int t = lane & 3;
    int mw = wid & 3;                 // row group (32 rows)
    int ncol0 = (wid >> 2) * 32;      // column base (32 cols)
    int prow = tid >> 3;              // gather: node slot (0..31)
    int c = tid & 7;                  // gather: uint4 chunk (8 bf16)

    // stage weights once per block (BN folded into W1), tf32-rounded
    for (int i = tid; i < FEAT * FEAT; i += 256) {
        int n = i & 63;
        float s = __ldg(gam + n) * rsqrtf(__ldg(var + n) + BN_EPS);
        W1_s[(i >> 6) * W_STRIDE + n] = __uint_as_float(f2tf32(__ldg(wa + i) * s));
        W2_s[(i >> 6) * W_STRIDE + n] = __uint_as_float(f2tf32(__ldg(wb + i)));
    }
    if (tid < FEAT) {
        float s = __ldg(gam + tid) * rsqrtf(__ldg(var + tid) + BN_EPS);
        b0_s[tid] = (__ldg(ba + tid) - __ldg(mu + tid)) * s + __ldg(bet + tid);
        b1_s[tid] = __ldg(bb + tid);
    }
    // visibility of W covered by the gather->GEMM sync inside the loop

    for (int tile = blockIdx.x; tile < NTILES; tile += GRID_CONV) {
        int node_base = tile * 128;

        // ============ gather phase: 32 nodes/pass, 4 passes ============
#pragma unroll
        for (int s = 0; s < 4; s++) {
            int row = s * 32 + prow;
            int node = node_base + row;
            float acc[8] = {0.f, 0.f, 0.f, 0.f, 0.f, 0.f, 0.f, 0.f};
            if (node < N_NODES) {
                const uint4* hn = (const uint4*)(h + (size_t)node * FEAT);
                bacc(acc, __ldg(hn + c));
                int dg = __ldg(deg + node);
                if (dg > CAP) dg = CAP;
                const int* lst = csr + (size_t)node * CAP;

                // level 1: first 16 indices in four int4 loads
                const int4* lst4 = (const int4*)lst;
                int4 I0 = __ldg(lst4 + 0);
                int4 I1 = __ldg(lst4 + 1);
                int4 I2 = __ldg(lst4 + 2);
                int4 I3 = __ldg(lst4 + 3);
                int idx[UNR] = {I0.x, I0.y, I0.z, I0.w,
                                I1.x, I1.y, I1.z, I1.w,
                                I2.x, I2.y, I2.z, I2.w,
                                I3.x, I3.y, I3.z, I3.w};

                // level 2: statically unrolled predicated gathers (1 LDG/edge)
#pragma unroll
                for (int k = 0; k < UNR; k++) {
                    uint4 v = make_uint4(0u, 0u, 0u, 0u);
                    if (k < dg)
                        v = __ldg((const uint4*)(h + (size_t)idx[k] * FEAT) + c);
                    bacc(acc, v);
                }
                // rare tail: deg > 16
                for (int k = UNR; k < dg; k++) {
                    int s0 = __ldg(lst + k);
                    bacc(acc, __ldg((const uint4*)(h + (size_t)s0 * FEAT) + c));
                }
            }
            float* arow = A_s + row * A_STRIDE + c * 8;
            *(float4*)(arow)     = make_float4(acc[0], acc[1], acc[2], acc[3]);
            *(float4*)(arow + 4) = make_float4(acc[4], acc[5], acc[6], acc[7]);
            if (c == 0)
                bat_s[row] = (node < N_NODES) ? __ldg(batch + node) : -1;
        }
        __syncthreads();   // tile gathered (also orders weight staging)

        // ============ GEMM phase ============
        const float* Aw = A_s + (mw * 32) * A_STRIDE;
        float* Aww = A_s + (mw * 32) * A_STRIDE;

        float acc[2][4][4];

#define GEMM_LAYER(WS)                                                        \
    {                                                                         \
        _Pragma("unroll")                                                     \
        for (int mt = 0; mt < 2; mt++)                                        \
            _Pragma("unroll")                                                 \
            for (int nt = 0; nt < 4; nt++)                                    \
                _Pragma("unroll")                                             \
                for (int e = 0; e < 4; e++) acc[mt][nt][e] = 0.0f;            \
        _Pragma("unroll")                                                     \
        for (int ks = 0; ks < 8; ks++) {                                      \
            uint32_t af[2][4];                                                \
            _Pragma("unroll")                                                 \
            for (int mt = 0; mt < 2; mt++) {                                  \
                const float* ap = Aw + (mt * 16 + g) * A_STRIDE + ks * 8 + t; \
                af[mt][0] = f2tf32(ap[0]);                                    \
                af[mt][1] = f2tf32(ap[8 * A_STRIDE]);                         \
                af[mt][2] = f2tf32(ap[4]);                                    \
                af[mt][3] = f2tf32(ap[8 * A_STRIDE + 4]);                     \
            }                                                                 \
            _Pragma("unroll")                                                 \
            for (int nt = 0; nt < 4; nt++) {                                  \
                int col = ncol0 + nt * 8 + g;                                 \
                uint32_t b0 = __float_as_uint(WS[(ks * 8 + t) * W_STRIDE + col]);     \
                uint32_t b1 = __float_as_uint(WS[(ks * 8 + t + 4) * W_STRIDE + col]); \
                mma_tf32(acc[0][nt], af[0], b0, b1);                          \
                mma_tf32(acc[1][nt], af[1], b0, b1);                          \
            }                                                                 \
        }                                                                     \
    }

        // ---- Layer 1 ----
        GEMM_LAYER(W1_s);
        __syncthreads();   // all warps done reading A1

        // bias + relu, write u in place
#pragma unroll
        for (int mt = 0; mt < 2; mt++) {
#pragma unroll
            for (int nt = 0; nt < 4; nt++) {
                int col = ncol0 + nt * 8 + 2 * t;
                float bc0 = b0_s[col], bc1 = b0_s[col + 1];
                float* r0 = Aww + (mt * 16 + g) * A_STRIDE + col;
                float* r1 = Aww + (mt * 16 + g + 8) * A_STRIDE + col;
                r0[0] = fmaxf(acc[mt][nt][0] + bc0, 0.0f);
                r0[1] = fmaxf(acc[mt][nt][1] + bc1, 0.0f);
                r1[0] = fmaxf(acc[mt][nt][2] + bc0, 0.0f);
                r1[1] = fmaxf(acc[mt][nt][3] + bc1, 0.0f);
            }
        }
        __syncthreads();   // u complete

        // ---- Layer 2 ----
        GEMM_LAYER(W2_s);

        // ---- epilogue ----
        if (mode == 0) {
#pragma unroll
            for (int mt = 0; mt < 2; mt++) {
                int node0 = node_base + mw * 32 + mt * 16 + g;
                int node1 = node0 + 8;
#pragma unroll
                for (int nt = 0; nt < 4; nt++) {
                    int col = ncol0 + nt * 8 + 2 * t;
                    float bc0 = b1_s[col], bc1 = b1_s[col + 1];
                    if (node0 < N_NODES) {
                        uint32_t r = pack_bf16x2(
                            fmaxf(acc[mt][nt][0] + bc0, 0.0f),
                            fmaxf(acc[mt][nt][1] + bc1, 0.0f));
                        *(uint32_t*)(out + (size_t)node0 * FEAT + col) = r;
                    }
                    if (node1 < N_NODES) {
                        uint32_t r = pack_bf16x2(
                            fmaxf(acc[mt][nt][2] + bc0, 0.0f),
                            fmaxf(acc[mt][nt][3] + bc1, 0.0f));
                        *(uint32_t*)(out + (size_t)node1 * FEAT + col) = r;
                    }
                }
            }
        } else {
            __syncthreads();   // all warps done reading A (layer 2)
#pragma unroll
            for (int mt = 0; mt < 2; mt++) {
#pragma unroll
                for (int nt = 0; nt < 4; nt++) {
                    int col = ncol0 + nt * 8 + 2 * t;
                    float bc0 = b1_s[col], bc1 = b1_s[col + 1];
                    float* r0 = Aww + (mt * 16 + g) * A_STRIDE + col;
                    float* r1 = Aww + (mt * 16 + g + 8) * A_STRIDE + col;
                    r0[0] = acc[mt][nt][0] + bc0;
                    r0[1] = acc[mt][nt][1] + bc1;
                    r1[0] = acc[mt][nt][2] + bc0;
                    r1[1] = acc[mt][nt][3] + bc1;
                }
            }
            __syncthreads();

            // segmented column reduction over sorted batch ids
            int col = tid & 63;
            int quarter = tid >> 6;       // 0..3, 32 rows each
            int cur = -1;
            float run = 0.0f;
#pragma unroll 8
            for (int r = 0; r < 32; r++) {
                int rr = quarter * 32 + r;
                int b = bat_s[rr];
                float v = A_s[rr * A_STRIDE + col];
                if (b != cur) {
                    if (cur >= 0) {
                        float* q = sums + (size_t)cur * FEAT + col;
                        asm volatile("red.global.add.f32 [%0], %1;"
                                     :: "l"(q), "f"(run) : "memory");
                    }
                    cur = b;
                    run = 0.0f;
                }
                run += v;
            }
            if (cur >= 0) {
                float* q = sums + (size_t)cur * FEAT + col;
                asm volatile("red.global.add.f32 [%0], %1;"
                             :: "l"(q), "f"(run) : "memory");
            }
        }
        __syncthreads();   // done with A before next tile's gather
#undef GEMM_LAYER
    }
}

// ---------------------------------------------------------------------------
__global__ __launch_bounds__(64) void classify_kernel(
    const float* __restrict__ sums,
    const float* __restrict__ cnts,
    const float* __restrict__ wc,
    const float* __restrict__ bc,
    float* __restrict__ out)
{
    int g = blockIdx.x;
    int tid = threadIdx.x;
    __shared__ float p[FEAT];
    float cnt = fmaxf(__ldg(cnts + g), 1.0f);
    p[tid] = sums[(size_t)g * FEAT + tid] / cnt;
    __syncthreads();
    if (tid < N_CLS) {
        float acc = bc[tid];
#pragma unroll
        for (int k = 0; k < FEAT; k++) {
            acc = fmaf(p[k], wc[k * N_CLS + tid], acc);
        }
        out[(size_t)g * N_CLS + tid] = acc;
    }
}

// ---------------------------------------------------------------------------
extern "C" void kernel_launch(void* const* d_in, const int* in_sizes, int n_in,
                              void* d_out, int out_size)
{
    const float* x   = (const float*)d_in[0];
    const int*   ei  = (const int*)d_in[1];
    const int*   bat = (const int*)d_in[2];
    const float* w0a = (const float*)d_in[3];
    const float* b0a = (const float*)d_in[4];
    const float* g0  = (const float*)d_in[5];
    const float* be0 = (const float*)d_in[6];
    const float* m0  = (const float*)d_in[7];
    const float* v0  = (const float*)d_in[8];
    const float* w0b = (const float*)d_in[9];
    const float* b0b = (const float*)d_in[10];
    const float* w1a = (const float*)d_in[11];
    const float* b1a = (const float*)d_in[12];
    const float* g1  = (const float*)d_in[13];
    const float* be1 = (const float*)d_in[14];
    const float* m1  = (const float*)d_in[15];
    const float* v1  = (const float*)d_in[16];
    const float* w1b = (const float*)d_in[17];
    const float* b1b = (const float*)d_in[18];
    const float* wc  = (const float*)d_in[19];
    const float* bc  = (const float*)d_in[20];
    float* out = (float*)d_out;

    const int* src = ei;            // edge_index[0]
    const int* dst = ei + N_EDGES;  // edge_index[1]

    float *p_sums, *p_cnts;
    __nv_bfloat16 *p_xb, *p_h1;
    int *p_deg, *p_csr;
    cudaGetSymbolAddress((void**)&p_xb,   g_xb);
    cudaGetSymbolAddress((void**)&p_h1,   g_h1);
    cudaGetSymbolAddress((void**)&p_sums, g_sums);
    cudaGetSymbolAddress((void**)&p_cnts, g_cnts);
    cudaGetSymbolAddress((void**)&p_deg,  g_deg);
    cudaGetSymbolAddress((void**)&p_csr,  g_csr);

    static bool attr_done = false;
    if (!attr_done) {
        cudaFuncSetAttribute(conv_kernel,
                             cudaFuncAttributeMaxDynamicSharedMemorySize,
                             SM_TOTAL);
        attr_done = true;
    }

    const int fill_blocks = (N_EDGES + 255) / 256;
    const int node_blocks = (N_NODES + 255) / 256;
    const int cvt_blocks = (N_NODES * FEAT / 8 + 255) / 256;

    // ---- prep: x->bf16, CSR build, pool init ----
    cudaMemsetAsync(p_deg, 0, (size_t)N_NODES * sizeof(int));
    cudaMemsetAsync(p_sums, 0, (size_t)N_GRAPHS * FEAT * sizeof(float));
    cudaMemsetAsync(p_cnts, 0, (size_t)N_GRAPHS * sizeof(float));
    cvt_kernel<<<cvt_blocks, 256>>>(x, p_xb);
    fill_kernel<<<fill_blocks, 256>>>(src, dst, p_deg, p_csr);
    count_kernel<<<node_blocks, 256>>>(bat, p_cnts);

    // ---- Conv 0 (fused gather + MLP), writes h1 in bf16 ----
    conv_kernel<<<GRID_CONV, 256, SM_TOTAL>>>(
        p_xb, p_deg, p_csr, w0a, b0a, g0, be0, m0, v0,
        w0b, b0b, p_h1, bat, p_sums, /*mode=*/0);

    // ---- Conv 1 (fused gather + MLP + pooled sum) ----
    conv_kernel<<<GRID_CONV, 256, SM_TOTAL>>>(
        p_h1, p_deg, p_csr, w1a, b1a, g1, be1, m1, v1,
        w1b, b1b, /*out unused*/ p_h1, bat, p_sums, /*mode=*/1);

    // ---- Classify ----
    classify_kernel<<<N_GRAPHS, 64>>>(p_sums, p_cnts, wc, bc, out);
}

// round 16
// speedup vs baseline: 2.2344x; 1.1073x over previous
#include <cuda_runtime.h>
#include <cuda_bf16.h>
#include <math.h>
#include <stdint.h>

#define N_NODES 100000
#define N_EDGES 1000000
#define FEAT 64
#define N_GRAPHS 512
#define N_CLS 10
#define BN_EPS 1e-5f
#define CAP 96
#define UNR 16

#define NTILES 782
#define GRID_CONV 592

// Scratch (device globals — no allocation allowed)
__device__ __nv_bfloat16 g_xb[N_NODES * FEAT];   // x in bf16
__device__ __nv_bfloat16 g_h1[N_NODES * FEAT];   // h1 in bf16
__device__ float g_sums[N_GRAPHS * FEAT];
__device__ float g_cnts[N_GRAPHS];
__device__ int   g_deg[N_NODES];
__device__ int   g_csr[N_NODES * CAP];

// ---------------------------------------------------------------------------
// helpers
// ---------------------------------------------------------------------------
__device__ __forceinline__ uint32_t f2tf32(float x) {
    uint32_t r;
    asm("cvt.rna.tf32.f32 %0, %1;" : "=r"(r) : "f"(x));
    return r;
}

__device__ __forceinline__ uint32_t pack_bf16x2(float lo, float hi) {
    uint32_t r;
    asm("cvt.rn.bf16x2.f32 %0, %1, %2;" : "=r"(r) : "f"(hi), "f"(lo));
    return r;
}

__device__ __forceinline__ void mma_tf32(float* c, const uint32_t* a,
                                         uint32_t b0, uint32_t b1) {
    asm("mma.sync.aligned.m16n8k8.row.col.f32.tf32.tf32.f32 "
        "{%0,%1,%2,%3}, {%4,%5,%6,%7}, {%8,%9}, {%0,%1,%2,%3};"
        : "+f"(c[0]), "+f"(c[1]), "+f"(c[2]), "+f"(c[3])
        : "r"(a[0]), "r"(a[1]), "r"(a[2]), "r"(a[3]), "r"(b0), "r"(b1));
}

// accumulate 8 bf16 (one uint4) into 4 packed f32x2 accumulators
__device__ __forceinline__ void bacc2(unsigned long long* a, uint4 v) {
    uint32_t w[4] = {v.x, v.y, v.z, v.w};
#pragma unroll
    for (int j = 0; j < 4; j++) {
        uint32_t lo = w[j] << 16;
        uint32_t hi = w[j] & 0xFFFF0000u;
        unsigned long long p;
        asm("mov.b64 %0, {%1, %2};" : "=l"(p) : "r"(lo), "r"(hi));
        asm("add.rn.f32x2 %0, %0, %1;" : "+l"(a[j]) : "l"(p));
    }
}

// extract one bf16 of a pair as f32 bits (exact; also valid tf32)
__device__ __forceinline__ uint32_t bsel(uint32_t v, uint32_t sh) {
    return (v << sh) & 0xFFFF0000u;
}

// SMEM layout (bytes). A tile stored as bf16 pairs (uint32), 36 uints/row.
#define AS_U     36
#define SM_A     0
#define SM_W1    18432
#define SM_W2    (SM_W1 + 18432)
#define SM_B0    (SM_W2 + 18432)
#define SM_B1    (SM_B0 + 256)
#define SM_BAT   (SM_B1 + 256)
#define SM_TOTAL (SM_BAT + 512)          // 56320 bytes -> 4 blocks/SM
#define W_STRIDE 72

// ---------------------------------------------------------------------------
// x -> bf16 conversion (one thread = 8 elements)
// ---------------------------------------------------------------------------
__global__ __launch_bounds__(256) void cvt_kernel(
    const float* __restrict__ x, __nv_bfloat16* __restrict__ xb)
{
    int i = blockIdx.x * 256 + threadIdx.x;
    if (i >= N_NODES * FEAT / 8) return;
    const float4* xp = (const float4*)x + 2 * i;
    float4 a = __ldg(xp);
    float4 b = __ldg(xp + 1);
    uint4 r;
    r.x = pack_bf16x2(a.x, a.y);
    r.y = pack_bf16x2(a.z, a.w);
    r.z = pack_bf16x2(b.x, b.y);
    r.w = pack_bf16x2(b.z, b.w);
    ((uint4*)xb)[i] = r;
}

// ---------------------------------------------------------------------------
// CSR fill: csr[dst*CAP + pos] = src
// ---------------------------------------------------------------------------
__global__ __launch_bounds__(256) void fill_kernel(
    const int* __restrict__ src, const int* __restrict__ dst,
    int* __restrict__ deg, int* __restrict__ csr)
{
    int e = blockIdx.x * blockDim.x + threadIdx.x;
    if (e >= N_EDGES) return;
    int d = __ldg(dst + e);
    int pos = atomicAdd(deg + d, 1);
    if (pos < CAP) csr[d * CAP + pos] = __ldg(src + e);
}

// ---------------------------------------------------------------------------
__global__ __launch_bounds__(256) void count_kernel(
    const int* __restrict__ batch, float* __restrict__ cnts)
{
    int i = blockIdx.x * blockDim.x + threadIdx.x;
    if (i < N_NODES) atomicAdd(cnts + __ldg(batch + i), 1.0f);
}

// ---------------------------------------------------------------------------
// Fused gather + GIN MLP, persistent, all-warp phases. h AND the SMEM A tile
// in bf16 (A as packed pairs). fp32x2 gather accumulation; tf32 GEMM reads
// bf16-as-f32 fragments (exact, no cvt).
// mode 0: out[node] = bf16(relu(mlp(t)))
// mode 1: segmented block-reduce mlp(t) rows by sorted batch -> red to sums
// ---------------------------------------------------------------------------
__global__ __launch_bounds__(256, 4) void conv_kernel(
    const __nv_bfloat16* __restrict__ h,
    const int* __restrict__ deg, const int* __restrict__ csr,
    const float* __restrict__ wa, const float* __restrict__ ba,
    const float* __restrict__ gam, const float* __restrict__ bet,
    const float* __restrict__ mu,  const float* __restrict__ var,
    const float* __restrict__ wb,  const float* __restrict__ bb,
    __nv_bfloat16* __restrict__ out, const int* __restrict__ batch,
    float* __restrict__ sums, int mode)
{
    extern __shared__ __align__(16) char sm[];
    uint32_t* A_u  = (uint32_t*)(sm + SM_A);
    float* W1_s = (float*)(sm + SM_W1);
    float* W2_s = (float*)(sm + SM_W2);
    float* b0_s = (float*)(sm + SM_B0);
    float* b1_s = (float*)(sm + SM_B1);
    int*   bat_s = (int*)(sm + SM_BAT);

    int tid = threadIdx.x;
    int wid = tid >> 5;
    int lane = tid & 31;
    int g = lane >> 2;
    int t = lane & 3;
    int mw = wid & 3;                 // row group (32 rows)
    int ncol0 = (wid >> 2) * 32;      // column base (32 cols)
    int prow = tid >> 3;              // gather: node slot (0..31)
    int c = tid & 7;                  // gather: uint4 chunk (8 bf16)
    uint32_t shv = (t & 1) ? 0u : 16u;  // fragment extract shift

    // stage weights once per block (BN folded into W1), tf32-rounded
    for (int i = tid; i < FEAT * FEAT; i += 256) {
        int n = i & 63;
        float s = __ldg(gam + n) * rsqrtf(__ldg(var + n) + BN_EPS);
        W1_s[(i >> 6) * W_STRIDE + n] = __uint_as_float(f2tf32(__ldg(wa + i) * s));
        W2_s[(i >> 6) * W_STRIDE + n] = __uint_as_float(f2tf32(__ldg(wb + i)));
    }
    if (tid < FEAT) {
        float s = __ldg(gam + tid) * rsqrtf(__ldg(var + tid) + BN_EPS);
        b0_s[tid] = (__ldg(ba + tid) - __ldg(mu + tid)) * s + __ldg(bet + tid);
        b1_s[tid] = __ldg(bb + tid);
    }
    // visibility of W covered by the gather->GEMM sync inside the loop

    for (int tile = blockIdx.x; tile < NTILES; tile += GRID_CONV) {
        int node_base = tile * 128;

        // ============ gather phase: 32 nodes/pass, 4 passes ============
#pragma unroll
        for (int s = 0; s < 4; s++) {
            int row = s * 32 + prow;
            int node = node_base + row;
            unsigned long long acc[4] = {0ull, 0ull, 0ull, 0ull};
            if (node < N_NODES) {
                const uint4* hn = (const uint4*)(h + (size_t)node * FEAT);
                bacc2(acc, __ldg(hn + c));
                int dg = __ldg(deg + node);
                if (dg > CAP) dg = CAP;
                const int* lst = csr + (size_t)node * CAP;

                // level 1: first 16 indices in four int4 loads
                const int4* lst4 = (const int4*)lst;
                int4 I0 = __ldg(lst4 + 0);
                int4 I1 = __ldg(lst4 + 1);
                int4 I2 = __ldg(lst4 + 2);
                int4 I3 = __ldg(lst4 + 3);
                int idx[UNR] = {I0.x, I0.y, I0.z, I0.w,
                                I1.x, I1.y, I1.z, I1.w,
                                I2.x, I2.y, I2.z, I2.w,
                                I3.x, I3.y, I3.z, I3.w};

                // level 2: statically unrolled predicated gathers (1 LDG/edge)
#pragma unroll
                for (int k = 0; k < UNR; k++) {
                    uint4 v = make_uint4(0u, 0u, 0u, 0u);
                    if (k < dg)
                        v = __ldg((const uint4*)(h + (size_t)idx[k] * FEAT) + c);
                    bacc2(acc, v);
                }
                // rare tail: deg > 16
                for (int k = UNR; k < dg; k++) {
                    int s0 = __ldg(lst + k);
                    bacc2(acc, __ldg((const uint4*)(h + (size_t)s0 * FEAT) + c));
                }
            }
            // pack 4x f32x2 accumulators -> 4 bf16 pairs -> one STS.128
            uint4 r;
            {
                float lo, hi;
                asm("mov.b64 {%0, %1}, %2;" : "=f"(lo), "=f"(hi) : "l"(acc[0]));
                r.x = pack_bf16x2(lo, hi);
                asm("mov.b64 {%0, %1}, %2;" : "=f"(lo), "=f"(hi) : "l"(acc[1]));
                r.y = pack_bf16x2(lo, hi);
                asm("mov.b64 {%0, %1}, %2;" : "=f"(lo), "=f"(hi) : "l"(acc[2]));
                r.z = pack_bf16x2(lo, hi);
                asm("mov.b64 {%0, %1}, %2;" : "=f"(lo), "=f"(hi) : "l"(acc[3]));
                r.w = pack_bf16x2(lo, hi);
            }
            *(uint4*)(A_u + row * AS_U + c * 4) = r;
            if (c == 0)
                bat_s[row] = (node < N_NODES) ? __ldg(batch + node) : -1;
        }
        __syncthreads();   // tile gathered (also orders weight staging)

        // ============ GEMM phase ============
        const uint32_t* Aw = A_u + (mw * 32) * AS_U;
        uint32_t* Aww = A_u + (mw * 32) * AS_U;

        float acc[2][4][4];

#define GEMM_LAYER(WS)                                                        \
    {                                                                         \
        _Pragma("unroll")                                                     \
        for (int mt = 0; mt < 2; mt++)                                        \
            _Pragma("unroll")                                                 \
            for (int nt = 0; nt < 4; nt++)                                    \
                _Pragma("unroll")                                             \
                for (int e = 0; e < 4; e++) acc[mt][nt][e] = 0.0f;            \
        _Pragma("unroll")                                                     \
        for (int ks = 0; ks < 8; ks++) {                                      \
            int p0 = 4 * ks + (t >> 1);                                       \
            uint32_t af[2][4];                                                \
            _Pragma("unroll")                                                 \
            for (int mt = 0; mt < 2; mt++) {                                  \
                const uint32_t* ap = Aw + (mt * 16 + g) * AS_U;               \
                af[mt][0] = bsel(ap[p0], shv);                                \
                af[mt][1] = bsel(ap[8 * AS_U + p0], shv);                     \
                af[mt][2] = bsel(ap[p0 + 2], shv);                            \
                af[mt][3] = bsel(ap[8 * AS_U + p0 + 2], shv);                 \
            }                                                                 \
            _Pragma("unroll")                                                 \
            for (int nt = 0; nt < 4; nt++) {                                  \
                int col = ncol0 + nt * 8 + g;                                 \
                uint32_t b0 = __float_as_uint(WS[(ks * 8 + t) * W_STRIDE + col]);     \
                uint32_t b1 = __float_as_uint(WS[(ks * 8 + t + 4) * W_STRIDE + col]); \
                mma_tf32(acc[0][nt], af[0], b0, b1);                          \
                mma_tf32(acc[1][nt], af[1], b0, b1);                          \
            }                                                                 \
        }                                                                     \
    }

        // ---- Layer 1 ----
        GEMM_LAYER(W1_s);
        __syncthreads();   // all warps done reading A1

        // bias + relu, pack bf16 pairs, write u in place
#pragma unroll
        for (int mt = 0; mt < 2; mt++) {
#pragma unroll
            for (int nt = 0; nt < 4; nt++) {
                int col = ncol0 + nt * 8 + 2 * t;
                int pu = (col >> 1);
                float bc0 = b0_s[col], bc1 = b0_s[col + 1];
                Aww[(mt * 16 + g) * AS_U + pu] =
                    pack_bf16x2(fmaxf(acc[mt][nt][0] + bc0, 0.0f),
                                fmaxf(acc[mt][nt][1] + bc1, 0.0f));
                Aww[(mt * 16 + g + 8) * AS_U + pu] =
                    pack_bf16x2(fmaxf(acc[mt][nt][2] + bc0, 0.0f),
                                fmaxf(acc[mt][nt][3] + bc1, 0.0f));
            }
        }
        __syncthreads();   // u complete

        // ---- Layer 2 ----
        GEMM_LAYER(W2_s);

        // ---- epilogue ----
        if (mode == 0) {
#pragma unroll
            for (int mt = 0; mt < 2; mt++) {
                int node0 = node_base + mw * 32 + mt * 16 + g;
                int node1 = node0 + 8;
#pragma unroll
                for (int nt = 0; nt < 4; nt++) {
                    int col = ncol0 + nt * 8 + 2 * t;
                    float bc0 = b1_s[col], bc1 = b1_s[col + 1];
                    if (node0 < N_NODES) {
                        uint32_t r = pack_bf16x2(
                            fmaxf(acc[mt][nt][0] + bc0, 0.0f),
                            fmaxf(acc[mt][nt][1] + bc1, 0.0f));
                        *(uint32_t*)(out + (size_t)node0 * FEAT + col) = r;
                    }
                    if (node1 < N_NODES) {
                        uint32_t r = pack_bf16x2(
                            fmaxf(acc[mt][nt][2] + bc0, 0.0f),
                            fmaxf(acc[mt][nt][3] + bc1, 0.0f));
                        *(uint32_t*)(out + (size_t)node1 * FEAT + col) = r;
                    }
                }
            }
        } else {
            __syncthreads();   // all warps done reading A (layer 2)
            // write y (bias, no relu) as bf16 pairs into A
#pragma unroll
            for (int mt = 0; mt < 2; mt++) {
#pragma unroll
                for (int nt = 0; nt < 4; nt++) {
                    int col = ncol0 + nt * 8 + 2 * t;
                    int pu = (col >> 1);
                    float bc0 = b1_s[col], bc1 = b1_s[col + 1];
                    Aww[(mt * 16 + g) * AS_U + pu] =
                        pack_bf16x2(acc[mt][nt][0] + bc0, acc[mt][nt][1] + bc1);
                    Aww[(mt * 16 + g + 8) * AS_U + pu] =
                        pack_bf16x2(acc[mt][nt][2] + bc0, acc[mt][nt][3] + bc1);
                }
            }
            __syncthreads();

            // segmented column reduction over sorted batch ids
            int col = tid & 63;
            int pair = col >> 1;
            uint32_t sh = (col & 1) ? 0u : 16u;
            int quarter = tid >> 6;       // 0..3, 32 rows each
            int cur = -1;
            float run = 0.0f;
#pragma unroll 8
            for (int r = 0; r < 32; r++) {
                int rr = quarter * 32 + r;
                int b = bat_s[rr];
                float v = __uint_as_float(bsel(A_u[rr * AS_U + pair], sh));
                if (b != cur) {
                    if (cur >= 0) {
                        float* q = sums + (size_t)cur * FEAT + col;
                        asm volatile("red.global.add.f32 [%0], %1;"
                                     :: "l"(q), "f"(run) : "memory");
                    }
                    cur = b;
                    run = 0.0f;
                }
                run += v;
            }
            if (cur >= 0) {
                float* q = sums + (size_t)cur * FEAT + col;
                asm volatile("red.global.add.f32 [%0], %1;"
                             :: "l"(q), "f"(run) : "memory");
            }
        }
        __syncthreads();   // done with A before next tile's gather
#undef GEMM_LAYER
    }
}

// ---------------------------------------------------------------------------
__global__ __launch_bounds__(64) void classify_kernel(
    const float* __restrict__ sums,
    const float* __restrict__ cnts,
    const float* __restrict__ wc,
    const float* __restrict__ bc,
    float* __restrict__ out)
{
    int g = blockIdx.x;
    int tid = threadIdx.x;
    __shared__ float p[FEAT];
    float cnt = fmaxf(__ldg(cnts + g), 1.0f);
    p[tid] = sums[(size_t)g * FEAT + tid] / cnt;
    __syncthreads();
    if (tid < N_CLS) {
        float acc = bc[tid];
#pragma unroll
        for (int k = 0; k < FEAT; k++) {
            acc = fmaf(p[k], wc[k * N_CLS + tid], acc);
        }
        out[(size_t)g * N_CLS + tid] = acc;
    }
}

// ---------------------------------------------------------------------------
extern "C" void kernel_launch(void* const* d_in, const int* in_sizes, int n_in,
                              void* d_out, int out_size)
{
    const float* x   = (const float*)d_in[0];
    const int*   ei  = (const int*)d_in[1];
    const int*   bat = (const int*)d_in[2];
    const float* w0a = (const float*)d_in[3];
    const float* b0a = (const float*)d_in[4];
    const float* g0  = (const float*)d_in[5];
    const float* be0 = (const float*)d_in[6];
    const float* m0  = (const float*)d_in[7];
    const float* v0  = (const float*)d_in[8];
    const float* w0b = (const float*)d_in[9];
    const float* b0b = (const float*)d_in[10];
    const float* w1a = (const float*)d_in[11];
    const float* b1a = (const float*)d_in[12];
    const float* g1  = (const float*)d_in[13];
    const float* be1 = (const float*)d_in[14];
    const float* m1  = (const float*)d_in[15];
    const float* v1  = (const float*)d_in[16];
    const float* w1b = (const float*)d_in[17];
    const float* b1b = (const float*)d_in[18];
    const float* wc  = (const float*)d_in[19];
    const float* bc  = (const float*)d_in[20];
    float* out = (float*)d_out;

    const int* src = ei;            // edge_index[0]
    const int* dst = ei + N_EDGES;  // edge_index[1]

    float *p_sums, *p_cnts;
    __nv_bfloat16 *p_xb, *p_h1;
    int *p_deg, *p_csr;
    cudaGetSymbolAddress((void**)&p_xb,   g_xb);
    cudaGetSymbolAddress((void**)&p_h1,   g_h1);
    cudaGetSymbolAddress((void**)&p_sums, g_sums);
    cudaGetSymbolAddress((void**)&p_cnts, g_cnts);
    cudaGetSymbolAddress((void**)&p_deg,  g_deg);
    cudaGetSymbolAddress((void**)&p_csr,  g_csr);

    static bool attr_done = false;
    if (!attr_done) {
        cudaFuncSetAttribute(conv_kernel,
                             cudaFuncAttributeMaxDynamicSharedMemorySize,
                             SM_TOTAL);
        attr_done = true;
    }

    const int fill_blocks = (N_EDGES + 255) / 256;
    const int node_blocks = (N_NODES + 255) / 256;
    const int cvt_blocks = (N_NODES * FEAT / 8 + 255) / 256;

    // ---- prep: x->bf16, CSR build, pool init ----
    cudaMemsetAsync(p_deg, 0, (size_t)N_NODES * sizeof(int));
    cudaMemsetAsync(p_sums, 0, (size_t)N_GRAPHS * FEAT * sizeof(float));
    cudaMemsetAsync(p_cnts, 0, (size_t)N_GRAPHS * sizeof(float));
    cvt_kernel<<<cvt_blocks, 256>>>(x, p_xb);
    fill_kernel<<<fill_blocks, 256>>>(src, dst, p_deg, p_csr);
    count_kernel<<<node_blocks, 256>>>(bat, p_cnts);

    // ---- Conv 0 (fused gather + MLP), writes h1 in bf16 ----
    conv_kernel<<<GRID_CONV, 256, SM_TOTAL>>>(
        p_xb, p_deg, p_csr, w0a, b0a, g0, be0, m0, v0,
        w0b, b0b, p_h1, bat, p_sums, /*mode=*/0);

    // ---- Conv 1 (fused gather + MLP + pooled sum) ----
    conv_kernel<<<GRID_CONV, 256, SM_TOTAL>>>(
        p_h1, p_deg, p_csr, w1a, b1a, g1, be1, m1, v1,
        w1b, b1b, /*out unused*/ p_h1, bat, p_sums, /*mode=*/1);

    // ---- Classify ----
    classify_kernel<<<N_GRAPHS, 64>>>(p_sums, p_cnts, wc, bc, out);
}